// round 12
// baseline (speedup 1.0000x reference)
#include <cuda_runtime.h>
#include <cuda_bf16.h>
#include <math.h>
#include <mma.h>

using namespace nvcuda;

// Problem dims (fixed)
#define BB    64      // batch
#define LL    64      // encoder seq len
#define VV    32000   // vocab
#define TT    32      // decoder steps
#define DEMB  128
#define DENC  256
#define DDEC  512
#define NHH   8
#define HDD   64
#define NPROJ 250     // 32000/128 proj tiles
#define KSPLIT 4

struct __align__(256) Scratch {
    float Xpre[LL*BB*2048];       // x @ Wih^T  [4096, 2048] (dir-blocked, gate-blocked)
    float WhhT[DENC*2048];        // [256, 2048]
    float WdecT[640*2048];        // [640, 2048] concat(WihT_dec, WhhT_dec)
    float WqT[512*512];
    float WoutT[512*512];
    float transferT[512*512];
    float kv[LL*BB*1024];         // k (0..511), v (512..1023)
    float hf[2][BB*DENC];
    float hb[2][BB*DENC];
    float cf[BB*DENC];
    float cb[BB*DENC];
    float z[BB*640];              // [xe(128) | h(512)] decoder input
    float c[BB*512];
    float hstar[BB*512];
    float ctx[BB*512];
    float gpart[KSPLIT*BB*2048];  // K-split partials for gates GEMM
    float pmax[BB*512];
    int   pidx[BB*512];
    __nv_bfloat16 Whi[(size_t)VV*512];   // proj_W split, [V,512]
    __nv_bfloat16 Wlo[(size_t)VV*512];
    __nv_bfloat16 hsphi[BB*512];         // h (post-LN) split, [64,512]
    __nv_bfloat16 hsplo[BB*512];
    __nv_bfloat16 xhi[LL*BB*DEMB];       // token embeddings split [4096,128]
    __nv_bfloat16 xlo[LL*BB*DEMB];
    __nv_bfloat16 memhi[LL*BB*512];      // encoder memory split [4096,512]
    __nv_bfloat16 memlo[LL*BB*512];
    __nv_bfloat16 Wihsphi[2048*DEMB];    // enc Wih split, rows = dir*1024 + orig row
    __nv_bfloat16 Wihsplo[2048*DEMB];
    __nv_bfloat16 Wkvsphi[1024*512];     // attn k/v weights split [1024,512]
    __nv_bfloat16 Wkvsplo[1024*512];
};

__device__ Scratch S;

__device__ __forceinline__ float sigf(float x){ return 1.0f/(1.0f + expf(-x)); }

// ---------------------------------------------------------------------------
// init: zero encoder states, seed decoder xe with start_emb
// ---------------------------------------------------------------------------
__global__ void k_init(const float* __restrict__ start_emb){
    int i = blockIdx.x*blockDim.x + threadIdx.x;
    int stride = gridDim.x*blockDim.x;
    for (int idx=i; idx < BB*DENC; idx += stride){
        S.hf[0][idx]=0.f; S.hb[0][idx]=0.f; S.cf[idx]=0.f; S.cb[idx]=0.f;
    }
    for (int idx=i; idx < BB*DEMB; idx += stride)
        S.z[(idx>>7)*640 + (idx&127)] = start_emb[idx&127];
}

// embed + split: x[l,b,:] = tok_emb[nx[b,l]] -> bf16 hi/lo
__global__ void k_embed(const int* __restrict__ nx, const float* __restrict__ tok_emb){
    int n = blockIdx.x;                 // n = l*B + b
    int e = threadIdx.x;                // 128 threads
    int l = n >> 6, b = n & 63;
    float v = tok_emb[(size_t)nx[b*LL + l]*DEMB + e];
    __nv_bfloat16 hi = __float2bfloat16(v);
    S.xhi[(size_t)n*DEMB + e] = hi;
    S.xlo[(size_t)n*DEMB + e] = __float2bfloat16(v - __bfloat162float(hi));
}

__global__ void k_wsplit(const float* __restrict__ W){
    size_t n = (size_t)VV*512;
    for (size_t i = (size_t)blockIdx.x*blockDim.x + threadIdx.x; i < n;
         i += (size_t)gridDim.x*blockDim.x){
        float w = W[i];
        __nv_bfloat16 hi = __float2bfloat16(w);
        float lo = w - __bfloat162float(hi);
        S.Whi[i] = hi;
        S.Wlo[i] = __float2bfloat16(lo);
    }
}

// straight row split of enc Wih (rows already i,f,g,o blocked)
__global__ void k_wihsplit(const float* __restrict__ W, int dir){
    int idx = blockIdx.x*blockDim.x + threadIdx.x;   // 1024*128
    if (idx >= 1024*128) return;
    float w = W[idx];
    __nv_bfloat16 hi = __float2bfloat16(w);
    size_t o = (size_t)dir*1024*DEMB + idx;
    S.Wihsphi[o] = hi;
    S.Wihsplo[o] = __float2bfloat16(w - __bfloat162float(hi));
}

// Wkvsp[n][k] = split(attn_in_w[512+n][k]),  n in [0,1024)
__global__ void k_packkvsp(const float* __restrict__ W){
    int idx = blockIdx.x*blockDim.x + threadIdx.x;   // 1024*512
    if (idx >= 1024*512) return;
    float w = W[(size_t)512*512 + idx];
    __nv_bfloat16 hi = __float2bfloat16(w);
    S.Wkvsphi[idx] = hi;
    S.Wkvsplo[idx] = __float2bfloat16(w - __bfloat162float(hi));
}

// ---------------------------------------------------------------------------
// generic 32x32 tiled transpose
// ---------------------------------------------------------------------------
__global__ void k_transpose(const float* __restrict__ src, int row0, int nrows,
                            int ncols, float* __restrict__ dst, int dld){
    __shared__ float tile[32][33];
    int j0 = blockIdx.x*32, k0 = blockIdx.y*32;
    int x = threadIdx.x;
    #pragma unroll
    for (int i=0;i<32;i+=8){
        int j = j0 + threadIdx.y + i;
        int k = k0 + x;
        tile[threadIdx.y+i][x] = (j<nrows && k<ncols) ? src[(size_t)(row0+j)*ncols + k] : 0.f;
    }
    __syncthreads();
    #pragma unroll
    for (int i=0;i<32;i+=8){
        int k = k0 + threadIdx.y + i;
        int j = j0 + x;
        if (k<ncols && j<nrows) dst[(size_t)k*dld + j] = tile[x][threadIdx.y+i];
    }
}

// ---------------------------------------------------------------------------
// Pipelined fp32 SGEMM (gates K-split GEMM): BM=BN=64, BK=16, 256 thr, 4x4.
// gridDim.z splits K; raw partial written to C + z*zstride.
// ---------------------------------------------------------------------------
__global__ void __launch_bounds__(256, 2) k_sgemm(
    const float* __restrict__ A, int lda,
    const float* __restrict__ B, int ldb,
    float* __restrict__ C, int ldc, long long zstride,
    int K, int Klen)
{
    __shared__ float As[2][16][68];
    __shared__ float Bs[2][16][64];
    int tid = threadIdx.x;
    int tx = tid & 15, ty = tid >> 4;
    int m0 = blockIdx.y*64, n0 = blockIdx.x*64;
    int kstart = blockIdx.z*Klen;
    int kend   = min(K, kstart + Klen);
    int ntiles = (kend - kstart) >> 4;
    float acc[4][4] = {};
    float aR[4], bR[4];

    #pragma unroll
    for (int u=0;u<4;u++){
        int idx = tid + u*256;
        aR[u] = A[(size_t)(m0 + (idx>>4))*lda + kstart + (idx&15)];
        bR[u] = B[(size_t)(kstart + (idx>>6))*ldb + n0 + (idx&63)];
    }
    #pragma unroll
    for (int u=0;u<4;u++){
        int idx = tid + u*256;
        As[0][idx&15][idx>>4] = aR[u];
        Bs[0][idx>>6][idx&63] = bR[u];
    }
    __syncthreads();

    for (int t=0; t<ntiles; t++){
        int cur = t & 1;
        if (t+1 < ntiles){
            int kb = kstart + (t+1)*16;
            #pragma unroll
            for (int u=0;u<4;u++){
                int idx = tid + u*256;
                aR[u] = A[(size_t)(m0 + (idx>>4))*lda + kb + (idx&15)];
                bR[u] = B[(size_t)(kb + (idx>>6))*ldb + n0 + (idx&63)];
            }
        }
        #pragma unroll
        for (int k=0;k<16;k++){
            float4 a4 = *(const float4*)&As[cur][k][ty*4];
            float4 b4 = *(const float4*)&Bs[cur][k][tx*4];
            float av[4] = {a4.x,a4.y,a4.z,a4.w};
            float bv[4] = {b4.x,b4.y,b4.z,b4.w};
            #pragma unroll
            for (int r=0;r<4;r++)
                #pragma unroll
                for (int c=0;c<4;c++)
                    acc[r][c] += av[r]*bv[c];
        }
        if (t+1 < ntiles){
            int nxt = cur ^ 1;
            #pragma unroll
            for (int u=0;u<4;u++){
                int idx = tid + u*256;
                As[nxt][idx&15][idx>>4] = aR[u];
                Bs[nxt][idx>>6][idx&63] = bR[u];
            }
        }
        __syncthreads();
    }

    float* Cp = C + (size_t)blockIdx.z*zstride;
    #pragma unroll
    for (int r=0;r<4;r++)
        #pragma unroll
        for (int c=0;c<4;c++)
            Cp[(size_t)(m0+ty*4+r)*ldc + n0+tx*4+c] = acc[r][c];
}

// ---------------------------------------------------------------------------
// Generic tensor-core split-bf16 GEMM:
//   C[M,N] = (Ahi+Alo)[M,K] @ ((Bhi+Blo)[N,K])^T + bias
// 3-product bf16 split, fp32 accumulate. BM=64 (blockIdx.y), BN=128, BK=32,
// 256 threads, cp.async double-buffered B staging, smem-staged epilogue.
// If pmax != nullptr (requires gridDim.y==1): per-block row argmax partials.
// ---------------------------------------------------------------------------
__global__ void __launch_bounds__(256, 2) k_gemmtc(
    const __nv_bfloat16* __restrict__ Ahi, const __nv_bfloat16* __restrict__ Alo,
    const __nv_bfloat16* __restrict__ Bhi, const __nv_bfloat16* __restrict__ Blo,
    int K,
    const float* __restrict__ bias,
    float* __restrict__ Cout, long long ldc,
    float* __restrict__ pmax, int* __restrict__ pidx)
{
    __shared__ __align__(16) char sraw[40960];
    typedef __nv_bfloat16 (*BsT)[2][128][40];   // [buf][hi/lo][n][k(+pad)]
    BsT Bs = (BsT)sraw;
    float (*Cs)[132] = (float(*)[132])sraw;

    int tid  = threadIdx.x;
    int warp = tid >> 5;
    int mw   = warp & 3;      // m tile (16 rows)
    int nw   = warp >> 2;     // n half (64 cols)
    int n0   = blockIdx.x * 128;
    int m0   = blockIdx.y * 64;
    int nk   = K >> 5;        // 32-wide k chunks

    wmma::fragment<wmma::accumulator,16,16,16,float> acc[4];
    #pragma unroll
    for (int j=0;j<4;j++) wmma::fill_fragment(acc[j], 0.0f);

    auto issue = [&](int buf, int kc){
        int k0 = kc*32;
        #pragma unroll
        for (int u=0;u<4;u++){
            int c = tid + u*256;          // 0..1023 chunks of 16B
            int hilo = c >> 9;
            int r    = (c >> 2) & 127;
            int v    = c & 3;
            const __nv_bfloat16* src = (hilo ? Blo : Bhi)
                + (size_t)(n0 + r)*K + k0 + v*8;
            unsigned dst = (unsigned)__cvta_generic_to_shared(&Bs[buf][hilo][r][v*8]);
            asm volatile("cp.async.cg.shared.global [%0], [%1], 16;" :: "r"(dst), "l"(src));
        }
        asm volatile("cp.async.commit_group;");
    };

    issue(0, 0);
    for (int t=0; t<nk; t++){
        int cur = t & 1;
        if (t < nk-1){
            issue(cur^1, t+1);
            asm volatile("cp.async.wait_group 1;");
        } else {
            asm volatile("cp.async.wait_group 0;");
        }
        __syncthreads();
        #pragma unroll
        for (int ks=0; ks<2; ks++){
            int k16 = t*32 + ks*16;
            wmma::fragment<wmma::matrix_a,16,16,16,__nv_bfloat16,wmma::row_major> ahi, alo;
            wmma::load_matrix_sync(ahi, Ahi + (size_t)(m0 + mw*16)*K + k16, K);
            wmma::load_matrix_sync(alo, Alo + (size_t)(m0 + mw*16)*K + k16, K);
            #pragma unroll
            for (int j=0;j<4;j++){
                wmma::fragment<wmma::matrix_b,16,16,16,__nv_bfloat16,wmma::col_major> bhi, blo;
                int nl = nw*64 + j*16;
                wmma::load_matrix_sync(bhi, &Bs[cur][0][nl][ks*16], 40);
                wmma::load_matrix_sync(blo, &Bs[cur][1][nl][ks*16], 40);
                wmma::mma_sync(acc[j], ahi, bhi, acc[j]);
                wmma::mma_sync(acc[j], ahi, blo, acc[j]);
                wmma::mma_sync(acc[j], alo, bhi, acc[j]);
            }
        }
        __syncthreads();
    }

    #pragma unroll
    for (int j=0;j<4;j++)
        wmma::store_matrix_sync(&Cs[mw*16][nw*64 + j*16], acc[j], 132, wmma::mem_row_major);
    __syncthreads();

    int r  = tid >> 2;        // 0..63
    int c0 = tid & 3;
    float best = -1e30f; int bi = 0;
    #pragma unroll
    for (int i=0;i<32;i++){
        int c = c0 + i*4;
        float v = Cs[r][c];
        if (bias) v += bias[n0 + c];
        Cout[(size_t)(m0 + r)*ldc + n0 + c] = v;
        if (v > best){ best = v; bi = n0 + c; }
    }
    if (pmax){
        #pragma unroll
        for (int off=1; off<4; off<<=1){
            float v2 = __shfl_xor_sync(0xffffffffu, best, off);
            int   i2 = __shfl_xor_sync(0xffffffffu, bi,   off);
            if (v2 > best || (v2 == best && i2 < bi)){ best = v2; bi = i2; }
        }
        if (c0 == 0){
            pmax[r*512 + blockIdx.x] = best;
            pidx[r*512 + blockIdx.x] = bi;
        }
    }
}

// ---------------------------------------------------------------------------
// encoder step (both directions): gates = Xpre + h@WhhT + b, LSTM cell.
// Ping-pong h buffers on t parity. Writes memory as bf16 hi/lo split.
// ---------------------------------------------------------------------------
__global__ void __launch_bounds__(256) k_encstep(int t,
        const float* __restrict__ bias_f, const float* __restrict__ bias_b){
    __shared__ float sh[16][256];
    int tid = threadIdx.x;
    int tx = tid & 31, ty = tid >> 5;        // ty 0..7
    int dir = blockIdx.z;
    int b0 = blockIdx.y * 16;
    int jh = blockIdx.x * 32 + tx;

    const float* hrd = dir ? S.hb[t & 1]     : S.hf[t & 1];
    float*       hwr = dir ? S.hb[(t+1)&1]   : S.hf[(t+1)&1];
    float*       cbuf = dir ? S.cb : S.cf;

    for (int idx = tid; idx < 16*256; idx += 256)
        sh[idx >> 8][idx & 255] = hrd[(b0 + (idx >> 8))*256 + (idx & 255)];
    __syncthreads();

    const float* W = S.WhhT + dir*1024 + jh;
    float a00=0,a01=0,a02=0,a03=0,a10=0,a11=0,a12=0,a13=0;
    #pragma unroll 4
    for (int k=0;k<256;k++){
        const float* wr = W + (size_t)k*2048;
        float w0 = wr[0], w1 = wr[256], w2 = wr[512], w3 = wr[768];
        float h0v = sh[ty][k], h1v = sh[ty+8][k];
        a00 += h0v*w0; a01 += h0v*w1; a02 += h0v*w2; a03 += h0v*w3;
        a10 += h1v*w0; a11 += h1v*w1; a12 += h1v*w2; a13 += h1v*w3;
    }

    int xrow = dir ? (LL - 1 - t) : t;
    const float* bias = dir ? bias_b : bias_f;
    float bi_ = bias[jh], bf_ = bias[256+jh], bg_ = bias[512+jh], bo_ = bias[768+jh];

    #pragma unroll
    for (int rr=0;rr<2;rr++){
        int b = b0 + ty + rr*8;
        const float* xp = S.Xpre + ((size_t)(xrow*BB + b))*2048 + dir*1024;
        float gi = (rr ? a10 : a00) + xp[jh]       + bi_;
        float gf = (rr ? a11 : a01) + xp[256+jh]   + bf_;
        float gg = (rr ? a12 : a02) + xp[512+jh]   + bg_;
        float go = (rr ? a13 : a03) + xp[768+jh]   + bo_;
        float cprev = cbuf[b*256 + jh];
        float cc = sigf(gf)*cprev + sigf(gi)*tanhf(gg);
        float hh = sigf(go)*tanhf(cc);
        cbuf[b*256 + jh] = cc;
        hwr[b*256 + jh]  = hh;
        size_t mo = ((size_t)xrow*BB + b)*512 + dir*256 + jh;
        __nv_bfloat16 hi = __float2bfloat16(hh);
        S.memhi[mo] = hi;
        S.memlo[mo] = __float2bfloat16(hh - __bfloat162float(hi));
    }
}

// ---------------------------------------------------------------------------
// h0 = tanh(concat(hf,hb) @ transferT) -> z[:,128:640] (+ bf16 split);
// c0 = style_emb[label]
// ---------------------------------------------------------------------------
__global__ void __launch_bounds__(256) k_h0(const int* __restrict__ label,
                                            const float* __restrict__ style_emb){
    __shared__ float sh[8][512];
    int tid = threadIdx.x, tx = tid & 31, ty = tid >> 5;
    int b0 = blockIdx.y*8;
    int j  = blockIdx.x*32 + tx;
    for (int idx=tid; idx<8*512; idx+=256){
        int r = idx >> 9, c = idx & 511;
        sh[r][c] = (c < 256) ? S.hf[0][(b0+r)*256 + c]
                             : S.hb[0][(b0+r)*256 + c - 256];
    }
    __syncthreads();
    float acc = 0.f;
    #pragma unroll 4
    for (int k=0;k<512;k++) acc += sh[ty][k]*S.transferT[(size_t)k*512 + j];
    int b = b0 + ty;
    float hv = tanhf(acc);
    S.z[b*640 + 128 + j] = hv;
    __nv_bfloat16 hi = __float2bfloat16(hv);
    S.hsphi[b*512 + j] = hi;
    S.hsplo[b*512 + j] = __float2bfloat16(hv - __bfloat162float(hi));
    S.c[b*512 + j] = style_emb[(size_t)label[b]*512 + j];
}

// ---------------------------------------------------------------------------
// reduce gates K-split partials + bias, then LSTM cell (i,f,g,o)
// ---------------------------------------------------------------------------
__global__ void k_cellred(const float* __restrict__ dec_b){
    int b = blockIdx.x, j = threadIdx.x;   // 64 blocks x 512 threads
    float gi = dec_b[j], gf = dec_b[512+j], gg = dec_b[1024+j], go = dec_b[1536+j];
    #pragma unroll
    for (int z=0; z<KSPLIT; z++){
        const float* g = S.gpart + (size_t)z*(BB*2048) + b*2048;
        gi += g[j]; gf += g[512+j]; gg += g[1024+j]; go += g[1536+j];
    }
    float c = sigf(gf)*S.c[b*512+j] + sigf(gi)*tanhf(gg);
    S.c[b*512+j] = c;
    S.hstar[b*512+j] = sigf(go)*tanhf(c);
}

// ---------------------------------------------------------------------------
// attention with fused q GEMM (q = hstar @ WqT + bq, scaled); column-major
// coalesced weight access. grid (NH, B), 64 threads.
// ---------------------------------------------------------------------------
__global__ void k_attn2(const float* __restrict__ bq){
    int h = blockIdx.x, b = blockIdx.y;
    int l = threadIdx.x;   // 64
    __shared__ float hs[512], sq[64], sc[64], red[64];
    for (int i=l; i<128; i+=64)
        ((float4*)hs)[i] = ((const float4*)(S.hstar + b*512))[i];
    __syncthreads();
    {
        int j = h*64 + l;
        float qv = bq[j];
        #pragma unroll 8
        for (int k=0;k<512;k++) qv += hs[k]*S.WqT[(size_t)k*512 + j];
        sq[l] = qv * 0.125f;
    }
    __syncthreads();
    const float* kp = S.kv + ((size_t)l*BB + b)*1024 + h*64;
    float s = 0.f;
    #pragma unroll
    for (int d=0;d<64;d++) s += sq[d]*kp[d];
    sc[l] = s; red[l] = s;
    __syncthreads();
    for (int off=32; off; off>>=1){
        if (l < off) red[l] = fmaxf(red[l], red[l+off]);
        __syncthreads();
    }
    float m = red[0];
    __syncthreads();
    float e = expf(s - m);
    sc[l] = e; red[l] = e;
    __syncthreads();
    for (int off=32; off; off>>=1){
        if (l < off) red[l] += red[l+off];
        __syncthreads();
    }
    float inv = 1.f/red[0];
    int d = l;
    float acc = 0.f;
    #pragma unroll 4
    for (int l2=0;l2<64;l2++)
        acc += sc[l2] * S.kv[((size_t)l2*BB + b)*1024 + 512 + h*64 + d];
    S.ctx[b*512 + h*64 + d] = acc * inv;
}

// ---------------------------------------------------------------------------
// fused: a = ctx @ WoutT + b_out (column-major coalesced); y = hstar + a;
// LayerNorm; write z[:,128:640] + bf16 split. grid (64), 512 threads.
// ---------------------------------------------------------------------------
__global__ void __launch_bounds__(512) k_outln2(const float* __restrict__ ob,
                        const float* __restrict__ lng, const float* __restrict__ lnb){
    int b = blockIdx.x, j = threadIdx.x;   // 512
    __shared__ float sctx[512];
    if (j < 128) ((float4*)sctx)[j] = ((const float4*)(S.ctx + b*512))[j];
    __syncthreads();
    float y = S.hstar[b*512 + j] + ob[j];
    #pragma unroll 8
    for (int k=0;k<512;k++) y += sctx[k]*S.WoutT[(size_t)k*512 + j];

    float v1 = y, v2 = y*y;
    #pragma unroll
    for (int off=16; off; off>>=1){
        v1 += __shfl_down_sync(0xffffffffu, v1, off);
        v2 += __shfl_down_sync(0xffffffffu, v2, off);
    }
    __shared__ float s1[16], s2[16];
    __shared__ float mb[2];
    int wid = j >> 5, lane = j & 31;
    if (!lane){ s1[wid] = v1; s2[wid] = v2; }
    __syncthreads();
    if (j == 0){
        float a=0.f, cq=0.f;
        #pragma unroll
        for (int i=0;i<16;i++){ a += s1[i]; cq += s2[i]; }
        float mean = a*(1.f/512.f);
        float var  = cq*(1.f/512.f) - mean*mean;
        mb[0] = mean; mb[1] = rsqrtf(var + 1e-5f);
    }
    __syncthreads();
    float hv = (y - mb[0])*mb[1]*lng[j] + lnb[j];
    S.z[b*640 + 128 + j] = hv;
    __nv_bfloat16 hi = __float2bfloat16(hv);
    S.hsphi[b*512 + j] = hi;
    S.hsplo[b*512 + j] = __float2bfloat16(hv - __bfloat162float(hi));
}

// ---------------------------------------------------------------------------
// argmax reduce over NPROJ partials + embedding feedback -> z[:,0:128]
// ---------------------------------------------------------------------------
__global__ void k_feedback(const float* __restrict__ tok_emb){
    int b = blockIdx.x, t = threadIdx.x;   // 128
    float best = -1e30f; int bi = 0x7fffffff;
    for (int i=t; i<NPROJ; i+=128){
        float v = S.pmax[b*512 + i]; int idx = S.pidx[b*512 + i];
        if (v > best || (v == best && idx < bi)){ best = v; bi = idx; }
    }
    __shared__ float sv[128]; __shared__ int si[128];
    sv[t] = best; si[t] = bi;
    __syncthreads();
    for (int off=64; off; off>>=1){
        if (t < off){
            if (sv[t+off] > sv[t] || (sv[t+off] == sv[t] && si[t+off] < si[t])){
                sv[t] = sv[t+off]; si[t] = si[t+off];
            }
        }
        __syncthreads();
    }
    int tok = si[0];
    S.z[b*640 + t] = tok_emb[(size_t)tok*DEMB + t];
}

// ---------------------------------------------------------------------------
// host launch
// ---------------------------------------------------------------------------
extern "C" void kernel_launch(void* const* d_in, const int* in_sizes, int n_in,
                              void* d_out, int out_size){
    const int*   nx         = (const int*)  d_in[0];
    const int*   label      = (const int*)  d_in[1];
    const float* start_emb  = (const float*)d_in[2];
    const float* tok_emb    = (const float*)d_in[3];
    const float* style_emb  = (const float*)d_in[4];
    const float* enc_Wih_f  = (const float*)d_in[5];
    const float* enc_Whh_f  = (const float*)d_in[6];
    const float* enc_b_f    = (const float*)d_in[7];
    const float* enc_Wih_b  = (const float*)d_in[8];
    const float* enc_Whh_b  = (const float*)d_in[9];
    const float* enc_b_b    = (const float*)d_in[10];
    const float* transfer_W = (const float*)d_in[11];
    const float* dec_Wih    = (const float*)d_in[12];
    const float* dec_Whh    = (const float*)d_in[13];
    const float* dec_b      = (const float*)d_in[14];
    const float* attn_in_w  = (const float*)d_in[15];
    const float* attn_in_b  = (const float*)d_in[16];
    const float* attn_out_w = (const float*)d_in[17];
    const float* attn_out_b = (const float*)d_in[18];
    const float* proj_W     = (const float*)d_in[19];
    const float* proj_b     = (const float*)d_in[20];
    const float* ln_g       = (const float*)d_in[21];
    const float* ln_b       = (const float*)d_in[22];
    float* out = (float*)d_out;

    Scratch* sp;
    cudaGetSymbolAddress((void**)&sp, S);

    dim3 tb(32, 8);

    // ---- setup ----
    k_init<<<64, 256>>>(start_emb);
    k_embed<<<LL*BB, 128>>>(nx, tok_emb);
    k_wsplit<<<4096, 256>>>(proj_W);
    k_wihsplit<<<(1024*128+255)/256, 256>>>(enc_Wih_f, 0);
    k_wihsplit<<<(1024*128+255)/256, 256>>>(enc_Wih_b, 1);
    k_packkvsp<<<(1024*512+255)/256, 256>>>(attn_in_w);

    k_transpose<<<dim3(32,  8),  tb>>>(enc_Whh_f, 0, 1024, 256, sp->WhhT,              2048);
    k_transpose<<<dim3(32,  8),  tb>>>(enc_Whh_b, 0, 1024, 256, sp->WhhT + 1024,       2048);
    k_transpose<<<dim3(64,  4),  tb>>>(dec_Wih,   0, 2048, 128, sp->WdecT,             2048);
    k_transpose<<<dim3(64, 16),  tb>>>(dec_Whh,   0, 2048, 512, sp->WdecT + 128*2048,  2048);
    k_transpose<<<dim3(16, 16),  tb>>>(attn_in_w,    0, 512, 512, sp->WqT,              512);
    k_transpose<<<dim3(16, 16),  tb>>>(attn_out_w,   0, 512, 512, sp->WoutT,            512);
    k_transpose<<<dim3(16, 16),  tb>>>(transfer_W,   0, 512, 512, sp->transferT,        512);

    // Xpre = x @ Wihsp^T   (M=4096, N=2048, K=128) — wmma split-bf16
    k_gemmtc<<<dim3(16, 64), 256>>>(sp->xhi, sp->xlo, sp->Wihsphi, sp->Wihsplo,
                                    128, nullptr, sp->Xpre, 2048LL,
                                    nullptr, nullptr);

    // ---- encoder recurrence (both dirs per launch) ----
    for (int t=0; t<LL; t++)
        k_encstep<<<dim3(8, 4, 2), 256>>>(t, enc_b_f, enc_b_b);

    // h0 / c0
    k_h0<<<dim3(16, 8), 256>>>(label, style_emb);

    // k,v = memory @ Wkvsp^T + [bk|bv]   (M=4096, N=1024, K=512) — wmma
    k_gemmtc<<<dim3(8, 64), 256>>>(sp->memhi, sp->memlo, sp->Wkvsphi, sp->Wkvsplo,
                                   512, attn_in_b + 512, sp->kv, 1024LL,
                                   nullptr, nullptr);

    // ---- decoder: 6 launches/step ----
    for (int t=0; t<TT; t++){
        // gates partials: z @ WdecT   (M=64, N=2048, K=640, split 4x160)
        k_sgemm<<<dim3(32, 1, KSPLIT), 256>>>(sp->z, 640, sp->WdecT, 2048,
                                              sp->gpart, 2048, (long long)BB*2048,
                                              640, 160);
        k_cellred<<<64, 512>>>(dec_b);

        // attention (q GEMM fused, coalesced WqT columns)
        k_attn2<<<dim3(NHH, BB), 64>>>(attn_in_b);

        // out GEMM + residual + LayerNorm fused (coalesced WoutT columns)
        k_outln2<<<64, 512>>>(attn_out_b, ln_g, ln_b);

        // logits[:,t,:] = h @ proj_W^T + proj_b  (wmma split-bf16 + argmax)
        k_gemmtc<<<dim3(NPROJ, 1), 256>>>(sp->hsphi, sp->hsplo, sp->Whi, sp->Wlo,
                                          512, proj_b, out + (size_t)t*VV,
                                          (long long)TT*VV, sp->pmax, sp->pidx);

        k_feedback<<<64, 128>>>(tok_emb);
    }
    (void)in_sizes; (void)n_in; (void)out_size;
}

// round 13
// speedup vs baseline: 1.2150x; 1.2150x over previous
#include <cuda_runtime.h>
#include <cuda_bf16.h>
#include <math.h>
#include <mma.h>

using namespace nvcuda;

// Problem dims (fixed)
#define BB    64      // batch
#define LL    64      // encoder seq len
#define VV    32000   // vocab
#define TT    32      // decoder steps
#define DEMB  128
#define DENC  256
#define DDEC  512
#define NHH   8
#define HDD   64
#define NPROJ 250     // 32000/128 proj tiles
#define KSPLIT 4

// k_gemmtc smem: 3 stages x (A: 2x64x40 bf16 = 10240 B, B: 2x128x40 bf16 = 20480 B)
#define GEMMTC_ASTG 10240
#define GEMMTC_BSTG 20480
#define GEMMTC_SMEM (3*GEMMTC_ASTG + 3*GEMMTC_BSTG)   // 92160

struct __align__(256) Scratch {
    float Xpre[LL*BB*2048];       // x @ Wih^T  [4096, 2048] (dir-blocked, gate-blocked)
    float WhhT[DENC*2048];        // [256, 2048]
    float WdecT[640*2048];        // [640, 2048] concat(WihT_dec, WhhT_dec)
    float WqT[512*512];
    float WoutT[512*512];
    float transferT[512*512];
    float kv[LL*BB*1024];         // k (0..511), v (512..1023)
    float hf[2][BB*DENC];
    float hb[2][BB*DENC];
    float cf[BB*DENC];
    float cb[BB*DENC];
    float z[BB*640];              // [xe(128) | h(512)] decoder input
    float c[BB*512];
    float hstar[BB*512];
    float ctx[BB*512];
    float gpart[KSPLIT*BB*2048];  // K-split partials for gates GEMM
    float qpart[KSPLIT*BB*512];
    float opart[KSPLIT*BB*512];
    float pmax[BB*512];
    int   pidx[BB*512];
    __nv_bfloat16 Whi[(size_t)VV*512];   // proj_W split, [V,512]
    __nv_bfloat16 Wlo[(size_t)VV*512];
    __nv_bfloat16 hsphi[BB*512];         // h (post-LN) split, [64,512]
    __nv_bfloat16 hsplo[BB*512];
    __nv_bfloat16 xhi[LL*BB*DEMB];       // token embeddings split [4096,128]
    __nv_bfloat16 xlo[LL*BB*DEMB];
    __nv_bfloat16 memhi[LL*BB*512];      // encoder memory split [4096,512]
    __nv_bfloat16 memlo[LL*BB*512];
    __nv_bfloat16 Wihsphi[2048*DEMB];    // enc Wih split, rows = dir*1024 + orig row
    __nv_bfloat16 Wihsplo[2048*DEMB];
    __nv_bfloat16 Wkvsphi[1024*512];     // attn k/v weights split [1024,512]
    __nv_bfloat16 Wkvsplo[1024*512];
};

__device__ Scratch S;

__device__ __forceinline__ float sigf(float x){ return 1.0f/(1.0f + expf(-x)); }

// ---------------------------------------------------------------------------
// init: zero encoder states, seed decoder xe with start_emb
// ---------------------------------------------------------------------------
__global__ void k_init(const float* __restrict__ start_emb){
    int i = blockIdx.x*blockDim.x + threadIdx.x;
    int stride = gridDim.x*blockDim.x;
    for (int idx=i; idx < BB*DENC; idx += stride){
        S.hf[0][idx]=0.f; S.hb[0][idx]=0.f; S.cf[idx]=0.f; S.cb[idx]=0.f;
    }
    for (int idx=i; idx < BB*DEMB; idx += stride)
        S.z[(idx>>7)*640 + (idx&127)] = start_emb[idx&127];
}

// embed + split: x[l,b,:] = tok_emb[nx[b,l]] -> bf16 hi/lo
__global__ void k_embed(const int* __restrict__ nx, const float* __restrict__ tok_emb){
    int n = blockIdx.x;                 // n = l*B + b
    int e = threadIdx.x;                // 128 threads
    int l = n >> 6, b = n & 63;
    float v = tok_emb[(size_t)nx[b*LL + l]*DEMB + e];
    __nv_bfloat16 hi = __float2bfloat16(v);
    S.xhi[(size_t)n*DEMB + e] = hi;
    S.xlo[(size_t)n*DEMB + e] = __float2bfloat16(v - __bfloat162float(hi));
}

__global__ void k_wsplit(const float* __restrict__ W){
    size_t n = (size_t)VV*512;
    for (size_t i = (size_t)blockIdx.x*blockDim.x + threadIdx.x; i < n;
         i += (size_t)gridDim.x*blockDim.x){
        float w = W[i];
        __nv_bfloat16 hi = __float2bfloat16(w);
        float lo = w - __bfloat162float(hi);
        S.Whi[i] = hi;
        S.Wlo[i] = __float2bfloat16(lo);
    }
}

// straight row split of enc Wih (rows already i,f,g,o blocked)
__global__ void k_wihsplit(const float* __restrict__ W, int dir){
    int idx = blockIdx.x*blockDim.x + threadIdx.x;   // 1024*128
    if (idx >= 1024*128) return;
    float w = W[idx];
    __nv_bfloat16 hi = __float2bfloat16(w);
    size_t o = (size_t)dir*1024*DEMB + idx;
    S.Wihsphi[o] = hi;
    S.Wihsplo[o] = __float2bfloat16(w - __bfloat162float(hi));
}

// Wkvsp[n][k] = split(attn_in_w[512+n][k]),  n in [0,1024)
__global__ void k_packkvsp(const float* __restrict__ W){
    int idx = blockIdx.x*blockDim.x + threadIdx.x;   // 1024*512
    if (idx >= 1024*512) return;
    float w = W[(size_t)512*512 + idx];
    __nv_bfloat16 hi = __float2bfloat16(w);
    S.Wkvsphi[idx] = hi;
    S.Wkvsplo[idx] = __float2bfloat16(w - __bfloat162float(hi));
}

// ---------------------------------------------------------------------------
// generic 32x32 tiled transpose
// ---------------------------------------------------------------------------
__global__ void k_transpose(const float* __restrict__ src, int row0, int nrows,
                            int ncols, float* __restrict__ dst, int dld){
    __shared__ float tile[32][33];
    int j0 = blockIdx.x*32, k0 = blockIdx.y*32;
    int x = threadIdx.x;
    #pragma unroll
    for (int i=0;i<32;i+=8){
        int j = j0 + threadIdx.y + i;
        int k = k0 + x;
        tile[threadIdx.y+i][x] = (j<nrows && k<ncols) ? src[(size_t)(row0+j)*ncols + k] : 0.f;
    }
    __syncthreads();
    #pragma unroll
    for (int i=0;i<32;i+=8){
        int k = k0 + threadIdx.y + i;
        int j = j0 + x;
        if (k<ncols && j<nrows) dst[(size_t)k*dld + j] = tile[x][threadIdx.y+i];
    }
}

// ---------------------------------------------------------------------------
// Pipelined fp32 SGEMM (decoder K-split GEMMs): BM=BN=64, BK=16, 256 thr, 4x4.
// gridDim.z splits K; raw partial written to C + z*zstride.
// ---------------------------------------------------------------------------
__global__ void __launch_bounds__(256, 2) k_sgemm(
    const float* __restrict__ A, int lda,
    const float* __restrict__ B, int ldb,
    float* __restrict__ C, int ldc, long long zstride,
    int K, int Klen)
{
    __shared__ float As[2][16][68];
    __shared__ float Bs[2][16][64];
    int tid = threadIdx.x;
    int tx = tid & 15, ty = tid >> 4;
    int m0 = blockIdx.y*64, n0 = blockIdx.x*64;
    int kstart = blockIdx.z*Klen;
    int kend   = min(K, kstart + Klen);
    int ntiles = (kend - kstart) >> 4;
    float acc[4][4] = {};
    float aR[4], bR[4];

    #pragma unroll
    for (int u=0;u<4;u++){
        int idx = tid + u*256;
        aR[u] = A[(size_t)(m0 + (idx>>4))*lda + kstart + (idx&15)];
        bR[u] = B[(size_t)(kstart + (idx>>6))*ldb + n0 + (idx&63)];
    }
    #pragma unroll
    for (int u=0;u<4;u++){
        int idx = tid + u*256;
        As[0][idx&15][idx>>4] = aR[u];
        Bs[0][idx>>6][idx&63] = bR[u];
    }
    __syncthreads();

    for (int t=0; t<ntiles; t++){
        int cur = t & 1;
        if (t+1 < ntiles){
            int kb = kstart + (t+1)*16;
            #pragma unroll
            for (int u=0;u<4;u++){
                int idx = tid + u*256;
                aR[u] = A[(size_t)(m0 + (idx>>4))*lda + kb + (idx&15)];
                bR[u] = B[(size_t)(kb + (idx>>6))*ldb + n0 + (idx&63)];
            }
        }
        #pragma unroll
        for (int k=0;k<16;k++){
            float4 a4 = *(const float4*)&As[cur][k][ty*4];
            float4 b4 = *(const float4*)&Bs[cur][k][tx*4];
            float av[4] = {a4.x,a4.y,a4.z,a4.w};
            float bv[4] = {b4.x,b4.y,b4.z,b4.w};
            #pragma unroll
            for (int r=0;r<4;r++)
                #pragma unroll
                for (int c=0;c<4;c++)
                    acc[r][c] += av[r]*bv[c];
        }
        if (t+1 < ntiles){
            int nxt = cur ^ 1;
            #pragma unroll
            for (int u=0;u<4;u++){
                int idx = tid + u*256;
                As[nxt][idx&15][idx>>4] = aR[u];
                Bs[nxt][idx>>6][idx&63] = bR[u];
            }
        }
        __syncthreads();
    }

    float* Cp = C + (size_t)blockIdx.z*zstride;
    #pragma unroll
    for (int r=0;r<4;r++)
        #pragma unroll
        for (int c=0;c<4;c++)
            Cp[(size_t)(m0+ty*4+r)*ldc + n0+tx*4+c] = acc[r][c];
}

// ---------------------------------------------------------------------------
// Generic tensor-core split-bf16 GEMM:
//   C[M,N] = (Ahi+Alo)[M,K] @ ((Bhi+Blo)[N,K])^T + bias
// 3-product bf16 split, fp32 accumulate. BM=64 (blockIdx.y), BN=128, BK=32,
// 256 threads. 3-stage cp.async pipeline staging BOTH A and B in smem,
// one __syncthreads per k-chunk. Dynamic smem (GEMMTC_SMEM).
// If pmax != nullptr (requires gridDim.y==1): per-block row argmax partials.
// ---------------------------------------------------------------------------
__global__ void __launch_bounds__(256, 2) k_gemmtc(
    const __nv_bfloat16* __restrict__ Ahi, const __nv_bfloat16* __restrict__ Alo,
    const __nv_bfloat16* __restrict__ Bhi, const __nv_bfloat16* __restrict__ Blo,
    int K,
    const float* __restrict__ bias,
    float* __restrict__ Cout, long long ldc,
    float* __restrict__ pmax, int* __restrict__ pidx)
{
    extern __shared__ __align__(128) char dsm[];
    __nv_bfloat16* Asm = (__nv_bfloat16*)dsm;                       // [3][2][64][40]
    __nv_bfloat16* Bsm = (__nv_bfloat16*)(dsm + 3*GEMMTC_ASTG);     // [3][2][128][40]
    float (*Cs)[132] = (float(*)[132])dsm;                          // epilogue alias

    int tid  = threadIdx.x;
    int warp = tid >> 5;
    int mw   = warp & 3;      // m tile (16 rows)
    int nw   = warp >> 2;     // n half (64 cols)
    int n0   = blockIdx.x * 128;
    int m0   = blockIdx.y * 64;
    int nk   = K >> 5;        // 32-wide k chunks

    wmma::fragment<wmma::accumulator,16,16,16,float> acc[4];
    #pragma unroll
    for (int j=0;j<4;j++) wmma::fill_fragment(acc[j], 0.0f);

    // stage chunk c (32 k-cols of A and B) into buffer c%3
    auto issue = [&](int c){
        int buf = c % 3;
        int k0 = c*32;
        __nv_bfloat16* bb = Bsm + buf*(2*128*40);
        __nv_bfloat16* aa = Asm + buf*(2*64*40);
        #pragma unroll
        for (int u=0;u<4;u++){
            int idx = tid + u*256;        // 0..1023: B 16B chunks
            int hilo = idx >> 9;
            int r    = (idx >> 2) & 127;
            int v    = idx & 3;
            const __nv_bfloat16* src = (hilo ? Blo : Bhi) + (size_t)(n0 + r)*K + k0 + v*8;
            unsigned dst = (unsigned)__cvta_generic_to_shared(bb + hilo*(128*40) + r*40 + v*8);
            asm volatile("cp.async.cg.shared.global [%0], [%1], 16;" :: "r"(dst), "l"(src));
        }
        #pragma unroll
        for (int u=0;u<2;u++){
            int idx = tid + u*256;        // 0..511: A 16B chunks
            int hilo = idx >> 8;
            int r    = (idx >> 2) & 63;
            int v    = idx & 3;
            const __nv_bfloat16* src = (hilo ? Alo : Ahi) + (size_t)(m0 + r)*K + k0 + v*8;
            unsigned dst = (unsigned)__cvta_generic_to_shared(aa + hilo*(64*40) + r*40 + v*8);
            asm volatile("cp.async.cg.shared.global [%0], [%1], 16;" :: "r"(dst), "l"(src));
        }
        asm volatile("cp.async.commit_group;");
    };

    issue(0);
    if (nk > 1) issue(1);

    for (int t=0; t<nk; t++){
        if (t+2 < nk) asm volatile("cp.async.wait_group 1;");
        else          asm volatile("cp.async.wait_group 0;");
        __syncthreads();
        if (t+2 < nk) issue(t+2);

        int buf = t % 3;
        const __nv_bfloat16* aa = Asm + buf*(2*64*40);
        const __nv_bfloat16* bb = Bsm + buf*(2*128*40);
        #pragma unroll
        for (int ks=0; ks<2; ks++){
            wmma::fragment<wmma::matrix_a,16,16,16,__nv_bfloat16,wmma::row_major> ahi, alo;
            wmma::load_matrix_sync(ahi, aa +            (mw*16)*40 + ks*16, 40);
            wmma::load_matrix_sync(alo, aa + 64*40 +    (mw*16)*40 + ks*16, 40);
            #pragma unroll
            for (int j=0;j<4;j++){
                wmma::fragment<wmma::matrix_b,16,16,16,__nv_bfloat16,wmma::col_major> bhi, blo;
                int nl = nw*64 + j*16;
                wmma::load_matrix_sync(bhi, bb +           nl*40 + ks*16, 40);
                wmma::load_matrix_sync(blo, bb + 128*40 +  nl*40 + ks*16, 40);
                wmma::mma_sync(acc[j], ahi, bhi, acc[j]);
                wmma::mma_sync(acc[j], ahi, blo, acc[j]);
                wmma::mma_sync(acc[j], alo, bhi, acc[j]);
            }
        }
    }
    __syncthreads();   // all warps done with smem before C staging overwrites it

    #pragma unroll
    for (int j=0;j<4;j++)
        wmma::store_matrix_sync(&Cs[mw*16][nw*64 + j*16], acc[j], 132, wmma::mem_row_major);
    __syncthreads();

    int r  = tid >> 2;        // 0..63
    int c0 = tid & 3;
    float best = -1e30f; int bi = 0;
    #pragma unroll
    for (int i=0;i<32;i++){
        int c = c0 + i*4;
        float v = Cs[r][c];
        if (bias) v += bias[n0 + c];
        Cout[(size_t)(m0 + r)*ldc + n0 + c] = v;
        if (v > best){ best = v; bi = n0 + c; }
    }
    if (pmax){
        #pragma unroll
        for (int off=1; off<4; off<<=1){
            float v2 = __shfl_xor_sync(0xffffffffu, best, off);
            int   i2 = __shfl_xor_sync(0xffffffffu, bi,   off);
            if (v2 > best || (v2 == best && i2 < bi)){ best = v2; bi = i2; }
        }
        if (c0 == 0){
            pmax[r*512 + blockIdx.x] = best;
            pidx[r*512 + blockIdx.x] = bi;
        }
    }
}

// ---------------------------------------------------------------------------
// encoder step (both directions): gates = Xpre + h@WhhT + b, LSTM cell.
// Ping-pong h buffers on t parity. Writes memory as bf16 hi/lo split.
// ---------------------------------------------------------------------------
__global__ void __launch_bounds__(256) k_encstep(int t,
        const float* __restrict__ bias_f, const float* __restrict__ bias_b){
    __shared__ float sh[16][256];
    int tid = threadIdx.x;
    int tx = tid & 31, ty = tid >> 5;        // ty 0..7
    int dir = blockIdx.z;
    int b0 = blockIdx.y * 16;
    int jh = blockIdx.x * 32 + tx;

    const float* hrd = dir ? S.hb[t & 1]     : S.hf[t & 1];
    float*       hwr = dir ? S.hb[(t+1)&1]   : S.hf[(t+1)&1];
    float*       cbuf = dir ? S.cb : S.cf;

    for (int idx = tid; idx < 16*256; idx += 256)
        sh[idx >> 8][idx & 255] = hrd[(b0 + (idx >> 8))*256 + (idx & 255)];
    __syncthreads();

    const float* W = S.WhhT + dir*1024 + jh;
    float a00=0,a01=0,a02=0,a03=0,a10=0,a11=0,a12=0,a13=0;
    #pragma unroll 4
    for (int k=0;k<256;k++){
        const float* wr = W + (size_t)k*2048;
        float w0 = wr[0], w1 = wr[256], w2 = wr[512], w3 = wr[768];
        float h0v = sh[ty][k], h1v = sh[ty+8][k];
        a00 += h0v*w0; a01 += h0v*w1; a02 += h0v*w2; a03 += h0v*w3;
        a10 += h1v*w0; a11 += h1v*w1; a12 += h1v*w2; a13 += h1v*w3;
    }

    int xrow = dir ? (LL - 1 - t) : t;
    const float* bias = dir ? bias_b : bias_f;
    float bi_ = bias[jh], bf_ = bias[256+jh], bg_ = bias[512+jh], bo_ = bias[768+jh];

    #pragma unroll
    for (int rr=0;rr<2;rr++){
        int b = b0 + ty + rr*8;
        const float* xp = S.Xpre + ((size_t)(xrow*BB + b))*2048 + dir*1024;
        float gi = (rr ? a10 : a00) + xp[jh]       + bi_;
        float gf = (rr ? a11 : a01) + xp[256+jh]   + bf_;
        float gg = (rr ? a12 : a02) + xp[512+jh]   + bg_;
        float go = (rr ? a13 : a03) + xp[768+jh]   + bo_;
        float cprev = cbuf[b*256 + jh];
        float cc = sigf(gf)*cprev + sigf(gi)*tanhf(gg);
        float hh = sigf(go)*tanhf(cc);
        cbuf[b*256 + jh] = cc;
        hwr[b*256 + jh]  = hh;
        size_t mo = ((size_t)xrow*BB + b)*512 + dir*256 + jh;
        __nv_bfloat16 hi = __float2bfloat16(hh);
        S.memhi[mo] = hi;
        S.memlo[mo] = __float2bfloat16(hh - __bfloat162float(hi));
    }
}

// ---------------------------------------------------------------------------
// h0 = tanh(concat(hf,hb) @ transferT) -> z[:,128:640] (+ bf16 split);
// c0 = style_emb[label]
// ---------------------------------------------------------------------------
__global__ void __launch_bounds__(256) k_h0(const int* __restrict__ label,
                                            const float* __restrict__ style_emb){
    __shared__ float sh[8][512];
    int tid = threadIdx.x, tx = tid & 31, ty = tid >> 5;
    int b0 = blockIdx.y*8;
    int j  = blockIdx.x*32 + tx;
    for (int idx=tid; idx<8*512; idx+=256){
        int r = idx >> 9, c = idx & 511;
        sh[r][c] = (c < 256) ? S.hf[0][(b0+r)*256 + c]
                             : S.hb[0][(b0+r)*256 + c - 256];
    }
    __syncthreads();
    float acc = 0.f;
    #pragma unroll 4
    for (int k=0;k<512;k++) acc += sh[ty][k]*S.transferT[(size_t)k*512 + j];
    int b = b0 + ty;
    float hv = tanhf(acc);
    S.z[b*640 + 128 + j] = hv;
    __nv_bfloat16 hi = __float2bfloat16(hv);
    S.hsphi[b*512 + j] = hi;
    S.hsplo[b*512 + j] = __float2bfloat16(hv - __bfloat162float(hi));
    S.c[b*512 + j] = style_emb[(size_t)label[b]*512 + j];
}

// ---------------------------------------------------------------------------
// reduce gates K-split partials + bias, then LSTM cell (i,f,g,o)
// ---------------------------------------------------------------------------
__global__ void k_cellred(const float* __restrict__ dec_b){
    int b = blockIdx.x, j = threadIdx.x;   // 64 blocks x 512 threads
    float gi = dec_b[j], gf = dec_b[512+j], gg = dec_b[1024+j], go = dec_b[1536+j];
    #pragma unroll
    for (int z=0; z<KSPLIT; z++){
        const float* g = S.gpart + (size_t)z*(BB*2048) + b*2048;
        gi += g[j]; gf += g[512+j]; gg += g[1024+j]; go += g[1536+j];
    }
    float c = sigf(gf)*S.c[b*512+j] + sigf(gi)*tanhf(gg);
    S.c[b*512+j] = c;
    S.hstar[b*512+j] = sigf(go)*tanhf(c);
}

// ---------------------------------------------------------------------------
// attention with fused q K-split reduce + bias/scale. grid (NH, B), 64 thr.
// ---------------------------------------------------------------------------
__global__ void k_attn(const float* __restrict__ bq){
    int h = blockIdx.x, b = blockIdx.y;
    int l = threadIdx.x;   // 64
    __shared__ float sq[64], sc[64], red[64];
    {
        int j = h*64 + l;
        float qv = bq[j];
        #pragma unroll
        for (int z=0; z<KSPLIT; z++)
            qv += S.qpart[(size_t)z*(BB*512) + b*512 + j];
        sq[l] = qv * 0.125f;
    }
    __syncthreads();
    const float* kp = S.kv + ((size_t)l*BB + b)*1024 + h*64;
    float s = 0.f;
    #pragma unroll
    for (int d=0;d<64;d++) s += sq[d]*kp[d];
    sc[l] = s; red[l] = s;
    __syncthreads();
    for (int off=32; off; off>>=1){
        if (l < off) red[l] = fmaxf(red[l], red[l+off]);
        __syncthreads();
    }
    float m = red[0];
    __syncthreads();
    float e = expf(s - m);
    sc[l] = e; red[l] = e;
    __syncthreads();
    for (int off=32; off; off>>=1){
        if (l < off) red[l] += red[l+off];
        __syncthreads();
    }
    float inv = 1.f/red[0];
    int d = l;
    float acc = 0.f;
    #pragma unroll 4
    for (int l2=0;l2<64;l2++)
        acc += sc[l2] * S.kv[((size_t)l2*BB + b)*1024 + 512 + h*64 + d];
    S.ctx[b*512 + h*64 + d] = acc * inv;
}

// ---------------------------------------------------------------------------
// reduce attn-out K-split partials + bias + residual, LayerNorm,
// write z[:,128:640] and bf16 hi/lo split for the proj GEMM.
// ---------------------------------------------------------------------------
__global__ void k_outln(const float* __restrict__ ob,
                        const float* __restrict__ lng, const float* __restrict__ lnb){
    int b = blockIdx.x, j = threadIdx.x;   // 64 blocks x 512 threads
    float y = S.hstar[b*512 + j] + ob[j];
    #pragma unroll
    for (int z=0; z<KSPLIT; z++)
        y += S.opart[(size_t)z*(BB*512) + b*512 + j];

    float v1 = y, v2 = y*y;
    #pragma unroll
    for (int off=16; off; off>>=1){
        v1 += __shfl_down_sync(0xffffffffu, v1, off);
        v2 += __shfl_down_sync(0xffffffffu, v2, off);
    }
    __shared__ float s1[16], s2[16];
    __shared__ float mb[2];
    int wid = j >> 5, lane = j & 31;
    if (!lane){ s1[wid] = v1; s2[wid] = v2; }
    __syncthreads();
    if (j == 0){
        float a=0.f, cq=0.f;
        #pragma unroll
        for (int i=0;i<16;i++){ a += s1[i]; cq += s2[i]; }
        float mean = a*(1.f/512.f);
        float var  = cq*(1.f/512.f) - mean*mean;
        mb[0] = mean; mb[1] = rsqrtf(var + 1e-5f);
    }
    __syncthreads();
    float hv = (y - mb[0])*mb[1]*lng[j] + lnb[j];
    S.z[b*640 + 128 + j] = hv;
    __nv_bfloat16 hi = __float2bfloat16(hv);
    S.hsphi[b*512 + j] = hi;
    S.hsplo[b*512 + j] = __float2bfloat16(hv - __bfloat162float(hi));
}

// ---------------------------------------------------------------------------
// argmax reduce over NPROJ partials + embedding feedback -> z[:,0:128]
// ---------------------------------------------------------------------------
__global__ void k_feedback(const float* __restrict__ tok_emb){
    int b = blockIdx.x, t = threadIdx.x;   // 128
    float best = -1e30f; int bi = 0x7fffffff;
    for (int i=t; i<NPROJ; i+=128){
        float v = S.pmax[b*512 + i]; int idx = S.pidx[b*512 + i];
        if (v > best || (v == best && idx < bi)){ best = v; bi = idx; }
    }
    __shared__ float sv[128]; __shared__ int si[128];
    sv[t] = best; si[t] = bi;
    __syncthreads();
    for (int off=64; off; off>>=1){
        if (t < off){
            if (sv[t+off] > sv[t] || (sv[t+off] == sv[t] && si[t+off] < si[t])){
                sv[t] = sv[t+off]; si[t] = si[t+off];
            }
        }
        __syncthreads();
    }
    int tok = si[0];
    S.z[b*640 + t] = tok_emb[(size_t)tok*DEMB + t];
}

// ---------------------------------------------------------------------------
// host launch
// ---------------------------------------------------------------------------
extern "C" void kernel_launch(void* const* d_in, const int* in_sizes, int n_in,
                              void* d_out, int out_size){
    const int*   nx         = (const int*)  d_in[0];
    const int*   label      = (const int*)  d_in[1];
    const float* start_emb  = (const float*)d_in[2];
    const float* tok_emb    = (const float*)d_in[3];
    const float* style_emb  = (const float*)d_in[4];
    const float* enc_Wih_f  = (const float*)d_in[5];
    const float* enc_Whh_f  = (const float*)d_in[6];
    const float* enc_b_f    = (const float*)d_in[7];
    const float* enc_Wih_b  = (const float*)d_in[8];
    const float* enc_Whh_b  = (const float*)d_in[9];
    const float* enc_b_b    = (const float*)d_in[10];
    const float* transfer_W = (const float*)d_in[11];
    const float* dec_Wih    = (const float*)d_in[12];
    const float* dec_Whh    = (const float*)d_in[13];
    const float* dec_b      = (const float*)d_in[14];
    const float* attn_in_w  = (const float*)d_in[15];
    const float* attn_in_b  = (const float*)d_in[16];
    const float* attn_out_w = (const float*)d_in[17];
    const float* attn_out_b = (const float*)d_in[18];
    const float* proj_W     = (const float*)d_in[19];
    const float* proj_b     = (const float*)d_in[20];
    const float* ln_g       = (const float*)d_in[21];
    const float* ln_b       = (const float*)d_in[22];
    float* out = (float*)d_out;

    Scratch* sp;
    cudaGetSymbolAddress((void**)&sp, S);
    cudaFuncSetAttribute(k_gemmtc, cudaFuncAttributeMaxDynamicSharedMemorySize, GEMMTC_SMEM);

    dim3 tb(32, 8);

    // ---- setup ----
    k_init<<<64, 256>>>(start_emb);
    k_embed<<<LL*BB, 128>>>(nx, tok_emb);
    k_wsplit<<<4096, 256>>>(proj_W);
    k_wihsplit<<<(1024*128+255)/256, 256>>>(enc_Wih_f, 0);
    k_wihsplit<<<(1024*128+255)/256, 256>>>(enc_Wih_b, 1);
    k_packkvsp<<<(1024*512+255)/256, 256>>>(attn_in_w);

    k_transpose<<<dim3(32,  8),  tb>>>(enc_Whh_f, 0, 1024, 256, sp->WhhT,              2048);
    k_transpose<<<dim3(32,  8),  tb>>>(enc_Whh_b, 0, 1024, 256, sp->WhhT + 1024,       2048);
    k_transpose<<<dim3(64,  4),  tb>>>(dec_Wih,   0, 2048, 128, sp->WdecT,             2048);
    k_transpose<<<dim3(64, 16),  tb>>>(dec_Whh,   0, 2048, 512, sp->WdecT + 128*2048,  2048);
    k_transpose<<<dim3(16, 16),  tb>>>(attn_in_w,    0, 512, 512, sp->WqT,              512);
    k_transpose<<<dim3(16, 16),  tb>>>(attn_out_w,   0, 512, 512, sp->WoutT,            512);
    k_transpose<<<dim3(16, 16),  tb>>>(transfer_W,   0, 512, 512, sp->transferT,        512);

    // Xpre = x @ Wihsp^T   (M=4096, N=2048, K=128) — wmma split-bf16
    k_gemmtc<<<dim3(16, 64), 256, GEMMTC_SMEM>>>(sp->xhi, sp->xlo, sp->Wihsphi, sp->Wihsplo,
                                                 128, nullptr, sp->Xpre, 2048LL,
                                                 nullptr, nullptr);

    // ---- encoder recurrence (both dirs per launch) ----
    for (int t=0; t<LL; t++)
        k_encstep<<<dim3(8, 4, 2), 256>>>(t, enc_b_f, enc_b_b);

    // h0 / c0
    k_h0<<<dim3(16, 8), 256>>>(label, style_emb);

    // k,v = memory @ Wkvsp^T + [bk|bv]   (M=4096, N=1024, K=512) — wmma
    k_gemmtc<<<dim3(8, 64), 256, GEMMTC_SMEM>>>(sp->memhi, sp->memlo, sp->Wkvsphi, sp->Wkvsplo,
                                                512, attn_in_b + 512, sp->kv, 1024LL,
                                                nullptr, nullptr);

    // ---- decoder: 8 launches/step (R11 structure) ----
    for (int t=0; t<TT; t++){
        // gates partials: z @ WdecT   (M=64, N=2048, K=640, split 4x160)
        k_sgemm<<<dim3(32, 1, KSPLIT), 256>>>(sp->z, 640, sp->WdecT, 2048,
                                              sp->gpart, 2048, (long long)BB*2048,
                                              640, 160);
        k_cellred<<<64, 512>>>(dec_b);

        // q partials: h* @ WqT  (M=64, N=512, K=512, split 4x128)
        k_sgemm<<<dim3(8, 1, KSPLIT), 256>>>(sp->hstar, 512, sp->WqT, 512,
                                             sp->qpart, 512, (long long)BB*512,
                                             512, 128);
        k_attn<<<dim3(NHH, BB), 64>>>(attn_in_b);

        // out partials: ctx @ WoutT  (M=64, N=512, K=512, split 4x128)
        k_sgemm<<<dim3(8, 1, KSPLIT), 256>>>(sp->ctx, 512, sp->WoutT, 512,
                                             sp->opart, 512, (long long)BB*512,
                                             512, 128);
        k_outln<<<64, 512>>>(attn_out_b, ln_g, ln_b);

        // logits[:,t,:] = h @ proj_W^T + proj_b  (wmma split-bf16 + argmax)
        k_gemmtc<<<dim3(NPROJ, 1), 256, GEMMTC_SMEM>>>(sp->hsphi, sp->hsplo, sp->Whi, sp->Wlo,
                                                       512, proj_b, out + (size_t)t*VV,
                                                       (long long)TT*VV, sp->pmax, sp->pidx);

        k_feedback<<<64, 128>>>(tok_emb);
    }
    (void)in_sizes; (void)n_in; (void)out_size;
}

// round 14
// speedup vs baseline: 1.4159x; 1.1653x over previous
#include <cuda_runtime.h>
#include <cuda_bf16.h>
#include <math.h>
#include <mma.h>

using namespace nvcuda;

// Problem dims (fixed)
#define BB    64      // batch
#define LL    64      // encoder seq len
#define VV    32000   // vocab
#define TT    32      // decoder steps
#define DEMB  128
#define DENC  256
#define DDEC  512
#define NHH   8
#define HDD   64
#define NPROJ 250     // 32000/128 proj tiles
#define KSPLIT 4

// k_gemmtc smem: 3 stages x (A: 2x64x40 bf16 = 10240 B, B: 2x128x40 bf16 = 20480 B)
#define GEMMTC_ASTG 10240
#define GEMMTC_BSTG 20480
#define GEMMTC_SMEM (3*GEMMTC_ASTG + 3*GEMMTC_BSTG)   // 92160

struct __align__(256) Scratch {
    float Xpre[LL*BB*2048];       // x @ Wih^T  [4096, 2048]; col = dir*1024 + j*4 + gate
    float Whh4[2*DENC*DENC*4];    // [dir][k][j][gate] gate-interleaved float4
    float WdecT[640*2048];        // [640, 2048] concat(WihT_dec, WhhT_dec)
    float WqT[512*512];
    float WoutT[512*512];
    float transferT[512*512];
    float kv[LL*BB*1024];         // k (0..511), v (512..1023)
    float hf[2][BB*DENC];
    float hb[2][BB*DENC];
    float cf[BB*DENC];
    float cb[BB*DENC];
    float z[BB*640];              // [xe(128) | h(512)] decoder input
    float c[BB*512];
    float hstar[BB*512];
    float ctx[BB*512];
    float gpart[KSPLIT*BB*2048];  // K-split partials for gates GEMM
    float qpart[KSPLIT*BB*512];
    float opart[KSPLIT*BB*512];
    float pmax[BB*512];
    int   pidx[BB*512];
    __nv_bfloat16 Whi[(size_t)VV*512];   // proj_W split, [V,512]
    __nv_bfloat16 Wlo[(size_t)VV*512];
    __nv_bfloat16 hsphi[BB*512];         // h (post-LN) split, [64,512]
    __nv_bfloat16 hsplo[BB*512];
    __nv_bfloat16 xhi[LL*BB*DEMB];       // token embeddings split [4096,128]
    __nv_bfloat16 xlo[LL*BB*DEMB];
    __nv_bfloat16 memhi[LL*BB*512];      // encoder memory split [4096,512]
    __nv_bfloat16 memlo[LL*BB*512];
    __nv_bfloat16 Wihsphi[2048*DEMB];    // enc Wih split; row = dir*1024 + j*4 + gate
    __nv_bfloat16 Wihsplo[2048*DEMB];
    __nv_bfloat16 Wkvsphi[1024*512];     // attn k/v weights split [1024,512]
    __nv_bfloat16 Wkvsplo[1024*512];
};

__device__ Scratch S;

__device__ __forceinline__ float sigf(float x){ return 1.0f/(1.0f + expf(-x)); }

// ---------------------------------------------------------------------------
// init: zero encoder states, seed decoder xe with start_emb
// ---------------------------------------------------------------------------
__global__ void k_init(const float* __restrict__ start_emb){
    int i = blockIdx.x*blockDim.x + threadIdx.x;
    int stride = gridDim.x*blockDim.x;
    for (int idx=i; idx < BB*DENC; idx += stride){
        S.hf[0][idx]=0.f; S.hb[0][idx]=0.f; S.cf[idx]=0.f; S.cb[idx]=0.f;
    }
    for (int idx=i; idx < BB*DEMB; idx += stride)
        S.z[(idx>>7)*640 + (idx&127)] = start_emb[idx&127];
}

// embed + split: x[l,b,:] = tok_emb[nx[b,l]] -> bf16 hi/lo
__global__ void k_embed(const int* __restrict__ nx, const float* __restrict__ tok_emb){
    int n = blockIdx.x;                 // n = l*B + b
    int e = threadIdx.x;                // 128 threads
    int l = n >> 6, b = n & 63;
    float v = tok_emb[(size_t)nx[b*LL + l]*DEMB + e];
    __nv_bfloat16 hi = __float2bfloat16(v);
    S.xhi[(size_t)n*DEMB + e] = hi;
    S.xlo[(size_t)n*DEMB + e] = __float2bfloat16(v - __bfloat162float(hi));
}

__global__ void k_wsplit(const float* __restrict__ W){
    size_t n = (size_t)VV*512;
    for (size_t i = (size_t)blockIdx.x*blockDim.x + threadIdx.x; i < n;
         i += (size_t)gridDim.x*blockDim.x){
        float w = W[i];
        __nv_bfloat16 hi = __float2bfloat16(w);
        float lo = w - __bfloat162float(hi);
        S.Whi[i] = hi;
        S.Wlo[i] = __float2bfloat16(lo);
    }
}

// enc Wih split, output row = dir*1024 + j*4 + g, src row = g*256 + j
__global__ void k_wihsplit(const float* __restrict__ W, int dir){
    int idx = blockIdx.x*blockDim.x + threadIdx.x;   // 1024*128
    if (idx >= 1024*128) return;
    int n = idx >> 7, k = idx & 127;
    int j = n >> 2, g = n & 3;
    float w = W[(size_t)(g*256 + j)*128 + k];
    __nv_bfloat16 hi = __float2bfloat16(w);
    size_t o = (size_t)(dir*1024 + n)*128 + k;
    S.Wihsphi[o] = hi;
    S.Wihsplo[o] = __float2bfloat16(w - __bfloat162float(hi));
}

// Whh4[dir][k][j][g] from enc_Whh_dir[g*256+j][k]
__global__ void k_packencwhh(const float* __restrict__ Whh, int dir){
    int idx = blockIdx.x*blockDim.x + threadIdx.x;   // 256*256
    if (idx >= 256*256) return;
    int k = idx >> 8, j = idx & 255;
    float4 w;
    w.x = Whh[(size_t)(0*256+j)*256 + k];
    w.y = Whh[(size_t)(1*256+j)*256 + k];
    w.z = Whh[(size_t)(2*256+j)*256 + k];
    w.w = Whh[(size_t)(3*256+j)*256 + k];
    ((float4*)S.Whh4)[(size_t)dir*256*256 + idx] = w;
}

// Wkvsp[n][k] = split(attn_in_w[512+n][k]),  n in [0,1024)
__global__ void k_packkvsp(const float* __restrict__ W){
    int idx = blockIdx.x*blockDim.x + threadIdx.x;   // 1024*512
    if (idx >= 1024*512) return;
    float w = W[(size_t)512*512 + idx];
    __nv_bfloat16 hi = __float2bfloat16(w);
    S.Wkvsphi[idx] = hi;
    S.Wkvsplo[idx] = __float2bfloat16(w - __bfloat162float(hi));
}

// ---------------------------------------------------------------------------
// generic 32x32 tiled transpose
// ---------------------------------------------------------------------------
__global__ void k_transpose(const float* __restrict__ src, int row0, int nrows,
                            int ncols, float* __restrict__ dst, int dld){
    __shared__ float tile[32][33];
    int j0 = blockIdx.x*32, k0 = blockIdx.y*32;
    int x = threadIdx.x;
    #pragma unroll
    for (int i=0;i<32;i+=8){
        int j = j0 + threadIdx.y + i;
        int k = k0 + x;
        tile[threadIdx.y+i][x] = (j<nrows && k<ncols) ? src[(size_t)(row0+j)*ncols + k] : 0.f;
    }
    __syncthreads();
    #pragma unroll
    for (int i=0;i<32;i+=8){
        int k = k0 + threadIdx.y + i;
        int j = j0 + x;
        if (k<ncols && j<nrows) dst[(size_t)k*dld + j] = tile[x][threadIdx.y+i];
    }
}

// ---------------------------------------------------------------------------
// Pipelined fp32 SGEMM (decoder K-split GEMMs): BM=BN=64, BK=16, 256 thr, 4x4.
// gridDim.z splits K; raw partial written to C + z*zstride.
// ---------------------------------------------------------------------------
__global__ void __launch_bounds__(256, 2) k_sgemm(
    const float* __restrict__ A, int lda,
    const float* __restrict__ B, int ldb,
    float* __restrict__ C, int ldc, long long zstride,
    int K, int Klen)
{
    __shared__ float As[2][16][68];
    __shared__ float Bs[2][16][64];
    int tid = threadIdx.x;
    int tx = tid & 15, ty = tid >> 4;
    int m0 = blockIdx.y*64, n0 = blockIdx.x*64;
    int kstart = blockIdx.z*Klen;
    int kend   = min(K, kstart + Klen);
    int ntiles = (kend - kstart) >> 4;
    float acc[4][4] = {};
    float aR[4], bR[4];

    #pragma unroll
    for (int u=0;u<4;u++){
        int idx = tid + u*256;
        aR[u] = A[(size_t)(m0 + (idx>>4))*lda + kstart + (idx&15)];
        bR[u] = B[(size_t)(kstart + (idx>>6))*ldb + n0 + (idx&63)];
    }
    #pragma unroll
    for (int u=0;u<4;u++){
        int idx = tid + u*256;
        As[0][idx&15][idx>>4] = aR[u];
        Bs[0][idx>>6][idx&63] = bR[u];
    }
    __syncthreads();

    for (int t=0; t<ntiles; t++){
        int cur = t & 1;
        if (t+1 < ntiles){
            int kb = kstart + (t+1)*16;
            #pragma unroll
            for (int u=0;u<4;u++){
                int idx = tid + u*256;
                aR[u] = A[(size_t)(m0 + (idx>>4))*lda + kb + (idx&15)];
                bR[u] = B[(size_t)(kb + (idx>>6))*ldb + n0 + (idx&63)];
            }
        }
        #pragma unroll
        for (int k=0;k<16;k++){
            float4 a4 = *(const float4*)&As[cur][k][ty*4];
            float4 b4 = *(const float4*)&Bs[cur][k][tx*4];
            float av[4] = {a4.x,a4.y,a4.z,a4.w};
            float bv[4] = {b4.x,b4.y,b4.z,b4.w};
            #pragma unroll
            for (int r=0;r<4;r++)
                #pragma unroll
                for (int c=0;c<4;c++)
                    acc[r][c] += av[r]*bv[c];
        }
        if (t+1 < ntiles){
            int nxt = cur ^ 1;
            #pragma unroll
            for (int u=0;u<4;u++){
                int idx = tid + u*256;
                As[nxt][idx&15][idx>>4] = aR[u];
                Bs[nxt][idx>>6][idx&63] = bR[u];
            }
        }
        __syncthreads();
    }

    float* Cp = C + (size_t)blockIdx.z*zstride;
    #pragma unroll
    for (int r=0;r<4;r++)
        #pragma unroll
        for (int c=0;c<4;c++)
            Cp[(size_t)(m0+ty*4+r)*ldc + n0+tx*4+c] = acc[r][c];
}

// ---------------------------------------------------------------------------
// Generic tensor-core split-bf16 GEMM:
//   C[M,N] = (Ahi+Alo)[M,K] @ ((Bhi+Blo)[N,K])^T + bias
// 3-product bf16 split, fp32 accumulate. BM=64 (blockIdx.y), BN=128, BK=32,
// 256 threads. 3-stage cp.async pipeline staging BOTH A and B in smem,
// one __syncthreads per k-chunk. Dynamic smem (GEMMTC_SMEM), carveout 100%
// so 2 blocks co-reside per SM.
// If pmax != nullptr (requires gridDim.y==1): per-block row argmax partials.
// ---------------------------------------------------------------------------
__global__ void __launch_bounds__(256, 2) k_gemmtc(
    const __nv_bfloat16* __restrict__ Ahi, const __nv_bfloat16* __restrict__ Alo,
    const __nv_bfloat16* __restrict__ Bhi, const __nv_bfloat16* __restrict__ Blo,
    int K,
    const float* __restrict__ bias,
    float* __restrict__ Cout, long long ldc,
    float* __restrict__ pmax, int* __restrict__ pidx)
{
    extern __shared__ __align__(128) char dsm[];
    __nv_bfloat16* Asm = (__nv_bfloat16*)dsm;                       // [3][2][64][40]
    __nv_bfloat16* Bsm = (__nv_bfloat16*)(dsm + 3*GEMMTC_ASTG);     // [3][2][128][40]
    float (*Cs)[132] = (float(*)[132])dsm;                          // epilogue alias

    int tid  = threadIdx.x;
    int warp = tid >> 5;
    int mw   = warp & 3;      // m tile (16 rows)
    int nw   = warp >> 2;     // n half (64 cols)
    int n0   = blockIdx.x * 128;
    int m0   = blockIdx.y * 64;
    int nk   = K >> 5;        // 32-wide k chunks

    wmma::fragment<wmma::accumulator,16,16,16,float> acc[4];
    #pragma unroll
    for (int j=0;j<4;j++) wmma::fill_fragment(acc[j], 0.0f);

    // stage chunk c (32 k-cols of A and B) into buffer c%3
    auto issue = [&](int c){
        int buf = c % 3;
        int k0 = c*32;
        __nv_bfloat16* bb = Bsm + buf*(2*128*40);
        __nv_bfloat16* aa = Asm + buf*(2*64*40);
        #pragma unroll
        for (int u=0;u<4;u++){
            int idx = tid + u*256;        // 0..1023: B 16B chunks
            int hilo = idx >> 9;
            int r    = (idx >> 2) & 127;
            int v    = idx & 3;
            const __nv_bfloat16* src = (hilo ? Blo : Bhi) + (size_t)(n0 + r)*K + k0 + v*8;
            unsigned dst = (unsigned)__cvta_generic_to_shared(bb + hilo*(128*40) + r*40 + v*8);
            asm volatile("cp.async.cg.shared.global [%0], [%1], 16;" :: "r"(dst), "l"(src));
        }
        #pragma unroll
        for (int u=0;u<2;u++){
            int idx = tid + u*256;        // 0..511: A 16B chunks
            int hilo = idx >> 8;
            int r    = (idx >> 2) & 63;
            int v    = idx & 3;
            const __nv_bfloat16* src = (hilo ? Alo : Ahi) + (size_t)(m0 + r)*K + k0 + v*8;
            unsigned dst = (unsigned)__cvta_generic_to_shared(aa + hilo*(64*40) + r*40 + v*8);
            asm volatile("cp.async.cg.shared.global [%0], [%1], 16;" :: "r"(dst), "l"(src));
        }
        asm volatile("cp.async.commit_group;");
    };

    issue(0);
    if (nk > 1) issue(1);

    for (int t=0; t<nk; t++){
        if (t+2 < nk) asm volatile("cp.async.wait_group 1;");
        else          asm volatile("cp.async.wait_group 0;");
        __syncthreads();
        if (t+2 < nk) issue(t+2);

        int buf = t % 3;
        const __nv_bfloat16* aa = Asm + buf*(2*64*40);
        const __nv_bfloat16* bb = Bsm + buf*(2*128*40);
        #pragma unroll
        for (int ks=0; ks<2; ks++){
            wmma::fragment<wmma::matrix_a,16,16,16,__nv_bfloat16,wmma::row_major> ahi, alo;
            wmma::load_matrix_sync(ahi, aa +            (mw*16)*40 + ks*16, 40);
            wmma::load_matrix_sync(alo, aa + 64*40 +    (mw*16)*40 + ks*16, 40);
            #pragma unroll
            for (int j=0;j<4;j++){
                wmma::fragment<wmma::matrix_b,16,16,16,__nv_bfloat16,wmma::col_major> bhi, blo;
                int nl = nw*64 + j*16;
                wmma::load_matrix_sync(bhi, bb +           nl*40 + ks*16, 40);
                wmma::load_matrix_sync(blo, bb + 128*40 +  nl*40 + ks*16, 40);
                wmma::mma_sync(acc[j], ahi, bhi, acc[j]);
                wmma::mma_sync(acc[j], ahi, blo, acc[j]);
                wmma::mma_sync(acc[j], alo, bhi, acc[j]);
            }
        }
    }
    __syncthreads();   // all warps done with smem before C staging overwrites it

    #pragma unroll
    for (int j=0;j<4;j++)
        wmma::store_matrix_sync(&Cs[mw*16][nw*64 + j*16], acc[j], 132, wmma::mem_row_major);
    __syncthreads();

    int r  = tid >> 2;        // 0..63
    int c0 = tid & 3;
    float best = -1e30f; int bi = 0;
    #pragma unroll
    for (int i=0;i<32;i++){
        int c = c0 + i*4;
        float v = Cs[r][c];
        if (bias) v += bias[n0 + c];
        Cout[(size_t)(m0 + r)*ldc + n0 + c] = v;
        if (v > best){ best = v; bi = n0 + c; }
    }
    if (pmax){
        #pragma unroll
        for (int off=1; off<4; off<<=1){
            float v2 = __shfl_xor_sync(0xffffffffu, best, off);
            int   i2 = __shfl_xor_sync(0xffffffffu, bi,   off);
            if (v2 > best || (v2 == best && i2 < bi)){ best = v2; bi = i2; }
        }
        if (c0 == 0){
            pmax[r*512 + blockIdx.x] = best;
            pidx[r*512 + blockIdx.x] = bi;
        }
    }
}

// ---------------------------------------------------------------------------
// encoder step: gates = Xpre + h@Whh^T + b, LSTM cell. Gate-interleaved
// float4 weight loads (Whh4) + float4 Xpre reads. Writes memory bf16 split.
// grid (8, 4, 2), 256 threads.
// ---------------------------------------------------------------------------
__global__ void __launch_bounds__(256) k_encstep(int t,
        const float* __restrict__ bias_f, const float* __restrict__ bias_b){
    __shared__ float sh[16][256];
    int tid = threadIdx.x;
    int tx = tid & 31, ty = tid >> 5;        // ty 0..7
    int dir = blockIdx.z;
    int b0 = blockIdx.y * 16;
    int jh = blockIdx.x * 32 + tx;

    const float* hrd = dir ? S.hb[t & 1]     : S.hf[t & 1];
    float*       hwr = dir ? S.hb[(t+1)&1]   : S.hf[(t+1)&1];
    float*       cbuf = dir ? S.cb : S.cf;

    for (int idx = tid; idx < 16*64; idx += 256){
        int r = idx >> 6, cc = idx & 63;
        ((float4*)sh[r])[cc] = ((const float4*)(hrd + (b0 + r)*256))[cc];
    }
    __syncthreads();

    const float4* W4 = (const float4*)S.Whh4 + (size_t)dir*256*256 + jh;
    float a00=0,a01=0,a02=0,a03=0,a10=0,a11=0,a12=0,a13=0;
    #pragma unroll 4
    for (int k=0;k<256;k++){
        float4 w = W4[k*256];
        float h0v = sh[ty][k], h1v = sh[ty+8][k];
        a00 += h0v*w.x; a01 += h0v*w.y; a02 += h0v*w.z; a03 += h0v*w.w;
        a10 += h1v*w.x; a11 += h1v*w.y; a12 += h1v*w.z; a13 += h1v*w.w;
    }

    int xrow = dir ? (LL - 1 - t) : t;
    const float* bias = dir ? bias_b : bias_f;
    float bi_ = bias[jh], bf_ = bias[256+jh], bg_ = bias[512+jh], bo_ = bias[768+jh];

    #pragma unroll
    for (int rr=0;rr<2;rr++){
        int b = b0 + ty + rr*8;
        float4 xg = *(const float4*)(S.Xpre + ((size_t)(xrow*BB + b))*2048 + dir*1024 + jh*4);
        float gi = (rr ? a10 : a00) + xg.x + bi_;
        float gf = (rr ? a11 : a01) + xg.y + bf_;
        float gg = (rr ? a12 : a02) + xg.z + bg_;
        float go = (rr ? a13 : a03) + xg.w + bo_;
        float cprev = cbuf[b*256 + jh];
        float cc = sigf(gf)*cprev + sigf(gi)*tanhf(gg);
        float hh = sigf(go)*tanhf(cc);
        cbuf[b*256 + jh] = cc;
        hwr[b*256 + jh]  = hh;
        size_t mo = ((size_t)xrow*BB + b)*512 + dir*256 + jh;
        __nv_bfloat16 hi = __float2bfloat16(hh);
        S.memhi[mo] = hi;
        S.memlo[mo] = __float2bfloat16(hh - __bfloat162float(hi));
    }
}

// ---------------------------------------------------------------------------
// h0 = tanh(concat(hf,hb) @ transferT) -> z[:,128:640] (+ bf16 split);
// c0 = style_emb[label]
// ---------------------------------------------------------------------------
__global__ void __launch_bounds__(256) k_h0(const int* __restrict__ label,
                                            const float* __restrict__ style_emb){
    __shared__ float sh[8][512];
    int tid = threadIdx.x, tx = tid & 31, ty = tid >> 5;
    int b0 = blockIdx.y*8;
    int j  = blockIdx.x*32 + tx;
    for (int idx=tid; idx<8*512; idx+=256){
        int r = idx >> 9, c = idx & 511;
        sh[r][c] = (c < 256) ? S.hf[0][(b0+r)*256 + c]
                             : S.hb[0][(b0+r)*256 + c - 256];
    }
    __syncthreads();
    float acc = 0.f;
    #pragma unroll 4
    for (int k=0;k<512;k++) acc += sh[ty][k]*S.transferT[(size_t)k*512 + j];
    int b = b0 + ty;
    float hv = tanhf(acc);
    S.z[b*640 + 128 + j] = hv;
    __nv_bfloat16 hi = __float2bfloat16(hv);
    S.hsphi[b*512 + j] = hi;
    S.hsplo[b*512 + j] = __float2bfloat16(hv - __bfloat162float(hi));
    S.c[b*512 + j] = style_emb[(size_t)label[b]*512 + j];
}

// ---------------------------------------------------------------------------
// reduce gates K-split partials + bias, then LSTM cell (i,f,g,o)
// ---------------------------------------------------------------------------
__global__ void k_cellred(const float* __restrict__ dec_b){
    int b = blockIdx.x, j = threadIdx.x;   // 64 blocks x 512 threads
    float gi = dec_b[j], gf = dec_b[512+j], gg = dec_b[1024+j], go = dec_b[1536+j];
    #pragma unroll
    for (int z=0; z<KSPLIT; z++){
        const float* g = S.gpart + (size_t)z*(BB*2048) + b*2048;
        gi += g[j]; gf += g[512+j]; gg += g[1024+j]; go += g[1536+j];
    }
    float c = sigf(gf)*S.c[b*512+j] + sigf(gi)*tanhf(gg);
    S.c[b*512+j] = c;
    S.hstar[b*512+j] = sigf(go)*tanhf(c);
}

// ---------------------------------------------------------------------------
// attention with fused q K-split reduce + bias/scale. grid (NH, B), 64 thr.
// ---------------------------------------------------------------------------
__global__ void k_attn(const float* __restrict__ bq){
    int h = blockIdx.x, b = blockIdx.y;
    int l = threadIdx.x;   // 64
    __shared__ float sq[64], sc[64], red[64];
    {
        int j = h*64 + l;
        float qv = bq[j];
        #pragma unroll
        for (int z=0; z<KSPLIT; z++)
            qv += S.qpart[(size_t)z*(BB*512) + b*512 + j];
        sq[l] = qv * 0.125f;
    }
    __syncthreads();
    const float* kp = S.kv + ((size_t)l*BB + b)*1024 + h*64;
    float s = 0.f;
    #pragma unroll
    for (int d=0;d<64;d++) s += sq[d]*kp[d];
    sc[l] = s; red[l] = s;
    __syncthreads();
    for (int off=32; off; off>>=1){
        if (l < off) red[l] = fmaxf(red[l], red[l+off]);
        __syncthreads();
    }
    float m = red[0];
    __syncthreads();
    float e = expf(s - m);
    sc[l] = e; red[l] = e;
    __syncthreads();
    for (int off=32; off; off>>=1){
        if (l < off) red[l] += red[l+off];
        __syncthreads();
    }
    float inv = 1.f/red[0];
    int d = l;
    float acc = 0.f;
    #pragma unroll 4
    for (int l2=0;l2<64;l2++)
        acc += sc[l2] * S.kv[((size_t)l2*BB + b)*1024 + 512 + h*64 + d];
    S.ctx[b*512 + h*64 + d] = acc * inv;
}

// ---------------------------------------------------------------------------
// reduce attn-out K-split partials + bias + residual, LayerNorm,
// write z[:,128:640] and bf16 hi/lo split for the proj GEMM.
// ---------------------------------------------------------------------------
__global__ void k_outln(const float* __restrict__ ob,
                        const float* __restrict__ lng, const float* __restrict__ lnb){
    int b = blockIdx.x, j = threadIdx.x;   // 64 blocks x 512 threads
    float y = S.hstar[b*512 + j] + ob[j];
    #pragma unroll
    for (int z=0; z<KSPLIT; z++)
        y += S.opart[(size_t)z*(BB*512) + b*512 + j];

    float v1 = y, v2 = y*y;
    #pragma unroll
    for (int off=16; off; off>>=1){
        v1 += __shfl_down_sync(0xffffffffu, v1, off);
        v2 += __shfl_down_sync(0xffffffffu, v2, off);
    }
    __shared__ float s1[16], s2[16];
    __shared__ float mb[2];
    int wid = j >> 5, lane = j & 31;
    if (!lane){ s1[wid] = v1; s2[wid] = v2; }
    __syncthreads();
    if (j == 0){
        float a=0.f, cq=0.f;
        #pragma unroll
        for (int i=0;i<16;i++){ a += s1[i]; cq += s2[i]; }
        float mean = a*(1.f/512.f);
        float var  = cq*(1.f/512.f) - mean*mean;
        mb[0] = mean; mb[1] = rsqrtf(var + 1e-5f);
    }
    __syncthreads();
    float hv = (y - mb[0])*mb[1]*lng[j] + lnb[j];
    S.z[b*640 + 128 + j] = hv;
    __nv_bfloat16 hi = __float2bfloat16(hv);
    S.hsphi[b*512 + j] = hi;
    S.hsplo[b*512 + j] = __float2bfloat16(hv - __bfloat162float(hi));
}

// ---------------------------------------------------------------------------
// argmax reduce over NPROJ partials + embedding feedback -> z[:,0:128]
// ---------------------------------------------------------------------------
__global__ void k_feedback(const float* __restrict__ tok_emb){
    int b = blockIdx.x, t = threadIdx.x;   // 128
    float best = -1e30f; int bi = 0x7fffffff;
    for (int i=t; i<NPROJ; i+=128){
        float v = S.pmax[b*512 + i]; int idx = S.pidx[b*512 + i];
        if (v > best || (v == best && idx < bi)){ best = v; bi = idx; }
    }
    __shared__ float sv[128]; __shared__ int si[128];
    sv[t] = best; si[t] = bi;
    __syncthreads();
    for (int off=64; off; off>>=1){
        if (t < off){
            if (sv[t+off] > sv[t] || (sv[t+off] == sv[t] && si[t+off] < si[t])){
                sv[t] = sv[t+off]; si[t] = si[t+off];
            }
        }
        __syncthreads();
    }
    int tok = si[0];
    S.z[b*640 + t] = tok_emb[(size_t)tok*DEMB + t];
}

// ---------------------------------------------------------------------------
// host launch
// ---------------------------------------------------------------------------
extern "C" void kernel_launch(void* const* d_in, const int* in_sizes, int n_in,
                              void* d_out, int out_size){
    const int*   nx         = (const int*)  d_in[0];
    const int*   label      = (const int*)  d_in[1];
    const float* start_emb  = (const float*)d_in[2];
    const float* tok_emb    = (const float*)d_in[3];
    const float* style_emb  = (const float*)d_in[4];
    const float* enc_Wih_f  = (const float*)d_in[5];
    const float* enc_Whh_f  = (const float*)d_in[6];
    const float* enc_b_f    = (const float*)d_in[7];
    const float* enc_Wih_b  = (const float*)d_in[8];
    const float* enc_Whh_b  = (const float*)d_in[9];
    const float* enc_b_b    = (const float*)d_in[10];
    const float* transfer_W = (const float*)d_in[11];
    const float* dec_Wih    = (const float*)d_in[12];
    const float* dec_Whh    = (const float*)d_in[13];
    const float* dec_b      = (const float*)d_in[14];
    const float* attn_in_w  = (const float*)d_in[15];
    const float* attn_in_b  = (const float*)d_in[16];
    const float* attn_out_w = (const float*)d_in[17];
    const float* attn_out_b = (const float*)d_in[18];
    const float* proj_W     = (const float*)d_in[19];
    const float* proj_b     = (const float*)d_in[20];
    const float* ln_g       = (const float*)d_in[21];
    const float* ln_b       = (const float*)d_in[22];
    float* out = (float*)d_out;

    Scratch* sp;
    cudaGetSymbolAddress((void**)&sp, S);
    cudaFuncSetAttribute(k_gemmtc, cudaFuncAttributeMaxDynamicSharedMemorySize, GEMMTC_SMEM);
    cudaFuncSetAttribute(k_gemmtc, cudaFuncAttributePreferredSharedMemoryCarveout, 100);

    dim3 tb(32, 8);

    // ---- setup ----
    k_init<<<64, 256>>>(start_emb);
    k_embed<<<LL*BB, 128>>>(nx, tok_emb);
    k_wsplit<<<4096, 256>>>(proj_W);
    k_wihsplit<<<(1024*128+255)/256, 256>>>(enc_Wih_f, 0);
    k_wihsplit<<<(1024*128+255)/256, 256>>>(enc_Wih_b, 1);
    k_packencwhh<<<(256*256+255)/256, 256>>>(enc_Whh_f, 0);
    k_packencwhh<<<(256*256+255)/256, 256>>>(enc_Whh_b, 1);
    k_packkvsp<<<(1024*512+255)/256, 256>>>(attn_in_w);

    k_transpose<<<dim3(64,  4),  tb>>>(dec_Wih,   0, 2048, 128, sp->WdecT,             2048);
    k_transpose<<<dim3(64, 16),  tb>>>(dec_Whh,   0, 2048, 512, sp->WdecT + 128*2048,  2048);
    k_transpose<<<dim3(16, 16),  tb>>>(attn_in_w,    0, 512, 512, sp->WqT,              512);
    k_transpose<<<dim3(16, 16),  tb>>>(attn_out_w,   0, 512, 512, sp->WoutT,            512);
    k_transpose<<<dim3(16, 16),  tb>>>(transfer_W,   0, 512, 512, sp->transferT,        512);

    // Xpre = x @ Wihsp^T   (M=4096, N=2048, K=128) — wmma split-bf16,
    // columns gate-interleaved (dir*1024 + j*4 + g)
    k_gemmtc<<<dim3(16, 64), 256, GEMMTC_SMEM>>>(sp->xhi, sp->xlo, sp->Wihsphi, sp->Wihsplo,
                                                 128, nullptr, sp->Xpre, 2048LL,
                                                 nullptr, nullptr);

    // ---- encoder recurrence (both dirs per launch) ----
    for (int t=0; t<LL; t++)
        k_encstep<<<dim3(8, 4, 2), 256>>>(t, enc_b_f, enc_b_b);

    // h0 / c0
    k_h0<<<dim3(16, 8), 256>>>(label, style_emb);

    // k,v = memory @ Wkvsp^T + [bk|bv]   (M=4096, N=1024, K=512) — wmma
    k_gemmtc<<<dim3(8, 64), 256, GEMMTC_SMEM>>>(sp->memhi, sp->memlo, sp->Wkvsphi, sp->Wkvsplo,
                                                512, attn_in_b + 512, sp->kv, 1024LL,
                                                nullptr, nullptr);

    // ---- decoder: 8 launches/step ----
    for (int t=0; t<TT; t++){
        // gates partials: z @ WdecT   (M=64, N=2048, K=640, split 4x160)
        k_sgemm<<<dim3(32, 1, KSPLIT), 256>>>(sp->z, 640, sp->WdecT, 2048,
                                              sp->gpart, 2048, (long long)BB*2048,
                                              640, 160);
        k_cellred<<<64, 512>>>(dec_b);

        // q partials: h* @ WqT  (M=64, N=512, K=512, split 4x128)
        k_sgemm<<<dim3(8, 1, KSPLIT), 256>>>(sp->hstar, 512, sp->WqT, 512,
                                             sp->qpart, 512, (long long)BB*512,
                                             512, 128);
        k_attn<<<dim3(NHH, BB), 64>>>(attn_in_b);

        // out partials: ctx @ WoutT  (M=64, N=512, K=512, split 4x128)
        k_sgemm<<<dim3(8, 1, KSPLIT), 256>>>(sp->ctx, 512, sp->WoutT, 512,
                                             sp->opart, 512, (long long)BB*512,
                                             512, 128);
        k_outln<<<64, 512>>>(attn_out_b, ln_g, ln_b);

        // logits[:,t,:] = h @ proj_W^T + proj_b  (wmma split-bf16 + argmax)
        k_gemmtc<<<dim3(NPROJ, 1), 256, GEMMTC_SMEM>>>(sp->hsphi, sp->hsplo, sp->Whi, sp->Wlo,
                                                       512, proj_b, out + (size_t)t*VV,
                                                       (long long)TT*VV, sp->pmax, sp->pidx);

        k_feedback<<<64, 128>>>(tok_emb);
    }
    (void)in_sizes; (void)n_in; (void)out_size;
}

// round 15
// speedup vs baseline: 1.4284x; 1.0088x over previous
#include <cuda_runtime.h>
#include <cuda_bf16.h>
#include <math.h>
#include <mma.h>

using namespace nvcuda;

// Problem dims (fixed)
#define BB    64      // batch
#define LL    64      // encoder seq len
#define VV    32000   // vocab
#define TT    32      // decoder steps
#define DEMB  128
#define DENC  256
#define DDEC  512
#define NHH   8
#define HDD   64
#define NPROJ 250     // 32000/128 proj tiles
#define KSPLIT 4

// k_gemmtc smem: 3 stages x (A: 2x64x40 bf16 = 10240 B, B: 2x128x40 bf16 = 20480 B)
#define GEMMTC_ASTG 10240
#define GEMMTC_BSTG 20480
#define GEMMTC_SMEM (3*GEMMTC_ASTG + 3*GEMMTC_BSTG)   // 92160

struct __align__(256) Scratch {
    float Xpre[LL*BB*2048];       // x @ Wih^T  [4096, 2048]; col = dir*1024 + j*4 + gate
    float Whh4[2*DENC*DENC*4];    // [dir][k][j][gate] gate-interleaved float4
    float WdecT[640*2048];        // [640, 2048] concat(WihT_dec, WhhT_dec)
    float WqT[512*512];
    float WoutT[512*512];
    float transferT[512*512];
    float kv[LL*BB*1024];         // k (0..511), v (512..1023)
    float hf[2][BB*DENC];
    float hb[2][BB*DENC];
    float cf[BB*DENC];
    float cb[BB*DENC];
    float z[BB*640];              // [xe(128) | h(512)] decoder input
    float c[BB*512];
    float hstar[BB*512];
    float ctx[BB*512];
    float gpart[KSPLIT*BB*2048];  // K-split partials for gates GEMM
    float qpart[KSPLIT*BB*512];
    float opart[KSPLIT*BB*512];
    float pmax[BB*512];
    int   pidx[BB*512];
    __nv_bfloat16 Whi[(size_t)VV*512];   // proj_W split, [V,512]
    __nv_bfloat16 Wlo[(size_t)VV*512];
    __nv_bfloat16 hsphi[BB*512];         // h (post-LN) split, [64,512]
    __nv_bfloat16 hsplo[BB*512];
    __nv_bfloat16 xhi[LL*BB*DEMB];       // token embeddings split [4096,128]
    __nv_bfloat16 xlo[LL*BB*DEMB];
    __nv_bfloat16 memhi[LL*BB*512];      // encoder memory split [4096,512]
    __nv_bfloat16 memlo[LL*BB*512];
    __nv_bfloat16 Wihsphi[2048*DEMB];    // enc Wih split; row = dir*1024 + j*4 + gate
    __nv_bfloat16 Wihsplo[2048*DEMB];
    __nv_bfloat16 Wkvsphi[1024*512];     // attn k/v weights split [1024,512]
    __nv_bfloat16 Wkvsplo[1024*512];
};

__device__ Scratch S;

// software grid barrier state (self-resetting; generation monotonic)
__device__ int g_bar_count = 0;
__device__ volatile int g_bar_gen = 0;

__device__ __forceinline__ void grid_barrier(int nblocks){
    __syncthreads();
    __threadfence();
    if (threadIdx.x == 0){
        int gen = g_bar_gen;
        if (atomicAdd(&g_bar_count, 1) == nblocks - 1){
            g_bar_count = 0;
            __threadfence();
            g_bar_gen = gen + 1;
        } else {
            while (g_bar_gen == gen) { }
        }
    }
    __syncthreads();
}

__device__ __forceinline__ float sigf(float x){ return 1.0f/(1.0f + expf(-x)); }

// ---------------------------------------------------------------------------
// init: zero encoder states, seed decoder xe with start_emb
// ---------------------------------------------------------------------------
__global__ void k_init(const float* __restrict__ start_emb){
    int i = blockIdx.x*blockDim.x + threadIdx.x;
    int stride = gridDim.x*blockDim.x;
    for (int idx=i; idx < BB*DENC; idx += stride){
        S.hf[0][idx]=0.f; S.hb[0][idx]=0.f; S.cf[idx]=0.f; S.cb[idx]=0.f;
    }
    for (int idx=i; idx < BB*DEMB; idx += stride)
        S.z[(idx>>7)*640 + (idx&127)] = start_emb[idx&127];
}

// embed + split: x[l,b,:] = tok_emb[nx[b,l]] -> bf16 hi/lo
__global__ void k_embed(const int* __restrict__ nx, const float* __restrict__ tok_emb){
    int n = blockIdx.x;                 // n = l*B + b
    int e = threadIdx.x;                // 128 threads
    int l = n >> 6, b = n & 63;
    float v = tok_emb[(size_t)nx[b*LL + l]*DEMB + e];
    __nv_bfloat16 hi = __float2bfloat16(v);
    S.xhi[(size_t)n*DEMB + e] = hi;
    S.xlo[(size_t)n*DEMB + e] = __float2bfloat16(v - __bfloat162float(hi));
}

__global__ void k_wsplit(const float* __restrict__ W){
    size_t n = (size_t)VV*512;
    for (size_t i = (size_t)blockIdx.x*blockDim.x + threadIdx.x; i < n;
         i += (size_t)gridDim.x*blockDim.x){
        float w = W[i];
        __nv_bfloat16 hi = __float2bfloat16(w);
        float lo = w - __bfloat162float(hi);
        S.Whi[i] = hi;
        S.Wlo[i] = __float2bfloat16(lo);
    }
}

// enc Wih split, output row = dir*1024 + j*4 + g, src row = g*256 + j
__global__ void k_wihsplit(const float* __restrict__ W, int dir){
    int idx = blockIdx.x*blockDim.x + threadIdx.x;   // 1024*128
    if (idx >= 1024*128) return;
    int n = idx >> 7, k = idx & 127;
    int j = n >> 2, g = n & 3;
    float w = W[(size_t)(g*256 + j)*128 + k];
    __nv_bfloat16 hi = __float2bfloat16(w);
    size_t o = (size_t)(dir*1024 + n)*128 + k;
    S.Wihsphi[o] = hi;
    S.Wihsplo[o] = __float2bfloat16(w - __bfloat162float(hi));
}

// Whh4[dir][k][j][g] from enc_Whh_dir[g*256+j][k]
__global__ void k_packencwhh(const float* __restrict__ Whh, int dir){
    int idx = blockIdx.x*blockDim.x + threadIdx.x;   // 256*256
    if (idx >= 256*256) return;
    int k = idx >> 8, j = idx & 255;
    float4 w;
    w.x = Whh[(size_t)(0*256+j)*256 + k];
    w.y = Whh[(size_t)(1*256+j)*256 + k];
    w.z = Whh[(size_t)(2*256+j)*256 + k];
    w.w = Whh[(size_t)(3*256+j)*256 + k];
    ((float4*)S.Whh4)[(size_t)dir*256*256 + idx] = w;
}

// Wkvsp[n][k] = split(attn_in_w[512+n][k]),  n in [0,1024)
__global__ void k_packkvsp(const float* __restrict__ W){
    int idx = blockIdx.x*blockDim.x + threadIdx.x;   // 1024*512
    if (idx >= 1024*512) return;
    float w = W[(size_t)512*512 + idx];
    __nv_bfloat16 hi = __float2bfloat16(w);
    S.Wkvsphi[idx] = hi;
    S.Wkvsplo[idx] = __float2bfloat16(w - __bfloat162float(hi));
}

// ---------------------------------------------------------------------------
// generic 32x32 tiled transpose
// ---------------------------------------------------------------------------
__global__ void k_transpose(const float* __restrict__ src, int row0, int nrows,
                            int ncols, float* __restrict__ dst, int dld){
    __shared__ float tile[32][33];
    int j0 = blockIdx.x*32, k0 = blockIdx.y*32;
    int x = threadIdx.x;
    #pragma unroll
    for (int i=0;i<32;i+=8){
        int j = j0 + threadIdx.y + i;
        int k = k0 + x;
        tile[threadIdx.y+i][x] = (j<nrows && k<ncols) ? src[(size_t)(row0+j)*ncols + k] : 0.f;
    }
    __syncthreads();
    #pragma unroll
    for (int i=0;i<32;i+=8){
        int k = k0 + threadIdx.y + i;
        int j = j0 + x;
        if (k<ncols && j<nrows) dst[(size_t)k*dld + j] = tile[x][threadIdx.y+i];
    }
}

// ---------------------------------------------------------------------------
// Pipelined fp32 SGEMM (decoder K-split GEMMs): BM=BN=64, BK=16, 256 thr, 4x4.
// gridDim.z splits K; raw partial written to C + z*zstride.
// ---------------------------------------------------------------------------
__global__ void __launch_bounds__(256, 2) k_sgemm(
    const float* __restrict__ A, int lda,
    const float* __restrict__ B, int ldb,
    float* __restrict__ C, int ldc, long long zstride,
    int K, int Klen)
{
    __shared__ float As[2][16][68];
    __shared__ float Bs[2][16][64];
    int tid = threadIdx.x;
    int tx = tid & 15, ty = tid >> 4;
    int m0 = blockIdx.y*64, n0 = blockIdx.x*64;
    int kstart = blockIdx.z*Klen;
    int kend   = min(K, kstart + Klen);
    int ntiles = (kend - kstart) >> 4;
    float acc[4][4] = {};
    float aR[4], bR[4];

    #pragma unroll
    for (int u=0;u<4;u++){
        int idx = tid + u*256;
        aR[u] = A[(size_t)(m0 + (idx>>4))*lda + kstart + (idx&15)];
        bR[u] = B[(size_t)(kstart + (idx>>6))*ldb + n0 + (idx&63)];
    }
    #pragma unroll
    for (int u=0;u<4;u++){
        int idx = tid + u*256;
        As[0][idx&15][idx>>4] = aR[u];
        Bs[0][idx>>6][idx&63] = bR[u];
    }
    __syncthreads();

    for (int t=0; t<ntiles; t++){
        int cur = t & 1;
        if (t+1 < ntiles){
            int kb = kstart + (t+1)*16;
            #pragma unroll
            for (int u=0;u<4;u++){
                int idx = tid + u*256;
                aR[u] = A[(size_t)(m0 + (idx>>4))*lda + kb + (idx&15)];
                bR[u] = B[(size_t)(kb + (idx>>6))*ldb + n0 + (idx&63)];
            }
        }
        #pragma unroll
        for (int k=0;k<16;k++){
            float4 a4 = *(const float4*)&As[cur][k][ty*4];
            float4 b4 = *(const float4*)&Bs[cur][k][tx*4];
            float av[4] = {a4.x,a4.y,a4.z,a4.w};
            float bv[4] = {b4.x,b4.y,b4.z,b4.w};
            #pragma unroll
            for (int r=0;r<4;r++)
                #pragma unroll
                for (int c=0;c<4;c++)
                    acc[r][c] += av[r]*bv[c];
        }
        if (t+1 < ntiles){
            int nxt = cur ^ 1;
            #pragma unroll
            for (int u=0;u<4;u++){
                int idx = tid + u*256;
                As[nxt][idx&15][idx>>4] = aR[u];
                Bs[nxt][idx>>6][idx&63] = bR[u];
            }
        }
        __syncthreads();
    }

    float* Cp = C + (size_t)blockIdx.z*zstride;
    #pragma unroll
    for (int r=0;r<4;r++)
        #pragma unroll
        for (int c=0;c<4;c++)
            Cp[(size_t)(m0+ty*4+r)*ldc + n0+tx*4+c] = acc[r][c];
}

// ---------------------------------------------------------------------------
// Generic tensor-core split-bf16 GEMM:
//   C[M,N] = (Ahi+Alo)[M,K] @ ((Bhi+Blo)[N,K])^T + bias
// 3-product bf16 split, fp32 accumulate. BM=64 (blockIdx.y), BN=128, BK=32,
// 256 threads. 3-stage cp.async pipeline, one __syncthreads per k-chunk.
// Dynamic smem (GEMMTC_SMEM), carveout 100% -> 2 blocks/SM.
// If pmax != nullptr (requires gridDim.y==1): per-block row argmax partials.
// ---------------------------------------------------------------------------
__global__ void __launch_bounds__(256, 2) k_gemmtc(
    const __nv_bfloat16* __restrict__ Ahi, const __nv_bfloat16* __restrict__ Alo,
    const __nv_bfloat16* __restrict__ Bhi, const __nv_bfloat16* __restrict__ Blo,
    int K,
    const float* __restrict__ bias,
    float* __restrict__ Cout, long long ldc,
    float* __restrict__ pmax, int* __restrict__ pidx)
{
    extern __shared__ __align__(128) char dsm[];
    __nv_bfloat16* Asm = (__nv_bfloat16*)dsm;                       // [3][2][64][40]
    __nv_bfloat16* Bsm = (__nv_bfloat16*)(dsm + 3*GEMMTC_ASTG);     // [3][2][128][40]
    float (*Cs)[132] = (float(*)[132])dsm;                          // epilogue alias

    int tid  = threadIdx.x;
    int warp = tid >> 5;
    int mw   = warp & 3;      // m tile (16 rows)
    int nw   = warp >> 2;     // n half (64 cols)
    int n0   = blockIdx.x * 128;
    int m0   = blockIdx.y * 64;
    int nk   = K >> 5;        // 32-wide k chunks

    wmma::fragment<wmma::accumulator,16,16,16,float> acc[4];
    #pragma unroll
    for (int j=0;j<4;j++) wmma::fill_fragment(acc[j], 0.0f);

    // stage chunk c (32 k-cols of A and B) into buffer c%3
    auto issue = [&](int c){
        int buf = c % 3;
        int k0 = c*32;
        __nv_bfloat16* bb = Bsm + buf*(2*128*40);
        __nv_bfloat16* aa = Asm + buf*(2*64*40);
        #pragma unroll
        for (int u=0;u<4;u++){
            int idx = tid + u*256;        // 0..1023: B 16B chunks
            int hilo = idx >> 9;
            int r    = (idx >> 2) & 127;
            int v    = idx & 3;
            const __nv_bfloat16* src = (hilo ? Blo : Bhi) + (size_t)(n0 + r)*K + k0 + v*8;
            unsigned dst = (unsigned)__cvta_generic_to_shared(bb + hilo*(128*40) + r*40 + v*8);
            asm volatile("cp.async.cg.shared.global [%0], [%1], 16;" :: "r"(dst), "l"(src));
        }
        #pragma unroll
        for (int u=0;u<2;u++){
            int idx = tid + u*256;        // 0..511: A 16B chunks
            int hilo = idx >> 8;
            int r    = (idx >> 2) & 63;
            int v    = idx & 3;
            const __nv_bfloat16* src = (hilo ? Alo : Ahi) + (size_t)(m0 + r)*K + k0 + v*8;
            unsigned dst = (unsigned)__cvta_generic_to_shared(aa + hilo*(64*40) + r*40 + v*8);
            asm volatile("cp.async.cg.shared.global [%0], [%1], 16;" :: "r"(dst), "l"(src));
        }
        asm volatile("cp.async.commit_group;");
    };

    issue(0);
    if (nk > 1) issue(1);

    for (int t=0; t<nk; t++){
        if (t+2 < nk) asm volatile("cp.async.wait_group 1;");
        else          asm volatile("cp.async.wait_group 0;");
        __syncthreads();
        if (t+2 < nk) issue(t+2);

        int buf = t % 3;
        const __nv_bfloat16* aa = Asm + buf*(2*64*40);
        const __nv_bfloat16* bb = Bsm + buf*(2*128*40);
        #pragma unroll
        for (int ks=0; ks<2; ks++){
            wmma::fragment<wmma::matrix_a,16,16,16,__nv_bfloat16,wmma::row_major> ahi, alo;
            wmma::load_matrix_sync(ahi, aa +            (mw*16)*40 + ks*16, 40);
            wmma::load_matrix_sync(alo, aa + 64*40 +    (mw*16)*40 + ks*16, 40);
            #pragma unroll
            for (int j=0;j<4;j++){
                wmma::fragment<wmma::matrix_b,16,16,16,__nv_bfloat16,wmma::col_major> bhi, blo;
                int nl = nw*64 + j*16;
                wmma::load_matrix_sync(bhi, bb +           nl*40 + ks*16, 40);
                wmma::load_matrix_sync(blo, bb + 128*40 +  nl*40 + ks*16, 40);
                wmma::mma_sync(acc[j], ahi, bhi, acc[j]);
                wmma::mma_sync(acc[j], ahi, blo, acc[j]);
                wmma::mma_sync(acc[j], alo, bhi, acc[j]);
            }
        }
    }
    __syncthreads();   // all warps done with smem before C staging overwrites it

    #pragma unroll
    for (int j=0;j<4;j++)
        wmma::store_matrix_sync(&Cs[mw*16][nw*64 + j*16], acc[j], 132, wmma::mem_row_major);
    __syncthreads();

    int r  = tid >> 2;        // 0..63
    int c0 = tid & 3;
    float best = -1e30f; int bi = 0;
    #pragma unroll
    for (int i=0;i<32;i++){
        int c = c0 + i*4;
        float v = Cs[r][c];
        if (bias) v += bias[n0 + c];
        Cout[(size_t)(m0 + r)*ldc + n0 + c] = v;
        if (v > best){ best = v; bi = n0 + c; }
    }
    if (pmax){
        #pragma unroll
        for (int off=1; off<4; off<<=1){
            float v2 = __shfl_xor_sync(0xffffffffu, best, off);
            int   i2 = __shfl_xor_sync(0xffffffffu, bi,   off);
            if (v2 > best || (v2 == best && i2 < bi)){ best = v2; bi = i2; }
        }
        if (c0 == 0){
            pmax[r*512 + blockIdx.x] = best;
            pidx[r*512 + blockIdx.x] = bi;
        }
    }
}

// ---------------------------------------------------------------------------
// PERSISTENT encoder: all 64 time steps in one launch, software grid barrier
// between steps. 64 blocks (all co-resident), 256 threads.
// block decomposition: jgrp = bid&7, bgrp = (bid>>3)&3, dir = bid>>5.
// ---------------------------------------------------------------------------
__global__ void __launch_bounds__(256) k_encoder(
        const float* __restrict__ bias_f, const float* __restrict__ bias_b){
    __shared__ float sh[16][256];
    int tid = threadIdx.x;
    int tx = tid & 31, ty = tid >> 5;        // ty 0..7
    int bid = blockIdx.x;
    int dir = bid >> 5;
    int b0  = ((bid >> 3) & 3) * 16;
    int jh  = (bid & 7) * 32 + tx;

    float* cbuf = dir ? S.cb : S.cf;
    const float* bias = dir ? bias_b : bias_f;
    float bi_ = bias[jh], bf_ = bias[256+jh], bg_ = bias[512+jh], bo_ = bias[768+jh];
    const float4* W4 = (const float4*)S.Whh4 + (size_t)dir*256*256 + jh;

    for (int t=0; t<LL; t++){
        const float* hrd = dir ? S.hb[t & 1]     : S.hf[t & 1];
        float*       hwr = dir ? S.hb[(t+1)&1]   : S.hf[(t+1)&1];

        for (int idx = tid; idx < 16*64; idx += 256){
            int r = idx >> 6, cc = idx & 63;
            ((float4*)sh[r])[cc] = ((const float4*)(hrd + (b0 + r)*256))[cc];
        }
        __syncthreads();

        float a00=0,a01=0,a02=0,a03=0,a10=0,a11=0,a12=0,a13=0;
        #pragma unroll 4
        for (int k=0;k<256;k++){
            float4 w = W4[k*256];
            float h0v = sh[ty][k], h1v = sh[ty+8][k];
            a00 += h0v*w.x; a01 += h0v*w.y; a02 += h0v*w.z; a03 += h0v*w.w;
            a10 += h1v*w.x; a11 += h1v*w.y; a12 += h1v*w.z; a13 += h1v*w.w;
        }

        int xrow = dir ? (LL - 1 - t) : t;
        #pragma unroll
        for (int rr=0;rr<2;rr++){
            int b = b0 + ty + rr*8;
            float4 xg = *(const float4*)(S.Xpre + ((size_t)(xrow*BB + b))*2048 + dir*1024 + jh*4);
            float gi = (rr ? a10 : a00) + xg.x + bi_;
            float gf = (rr ? a11 : a01) + xg.y + bf_;
            float gg = (rr ? a12 : a02) + xg.z + bg_;
            float go = (rr ? a13 : a03) + xg.w + bo_;
            float cprev = cbuf[b*256 + jh];
            float cc = sigf(gf)*cprev + sigf(gi)*tanhf(gg);
            float hh = sigf(go)*tanhf(cc);
            cbuf[b*256 + jh] = cc;
            hwr[b*256 + jh]  = hh;
            size_t mo = ((size_t)xrow*BB + b)*512 + dir*256 + jh;
            __nv_bfloat16 hi = __float2bfloat16(hh);
            S.memhi[mo] = hi;
            S.memlo[mo] = __float2bfloat16(hh - __bfloat162float(hi));
        }
        grid_barrier(64);   // includes __syncthreads: sh safe to refill
    }
}

// ---------------------------------------------------------------------------
// h0 = tanh(concat(hf,hb) @ transferT) -> z[:,128:640] (+ bf16 split);
// c0 = style_emb[label]
// ---------------------------------------------------------------------------
__global__ void __launch_bounds__(256) k_h0(const int* __restrict__ label,
                                            const float* __restrict__ style_emb){
    __shared__ float sh[8][512];
    int tid = threadIdx.x, tx = tid & 31, ty = tid >> 5;
    int b0 = blockIdx.y*8;
    int j  = blockIdx.x*32 + tx;
    for (int idx=tid; idx<8*512; idx+=256){
        int r = idx >> 9, c = idx & 511;
        sh[r][c] = (c < 256) ? S.hf[0][(b0+r)*256 + c]
                             : S.hb[0][(b0+r)*256 + c - 256];
    }
    __syncthreads();
    float acc = 0.f;
    #pragma unroll 4
    for (int k=0;k<512;k++) acc += sh[ty][k]*S.transferT[(size_t)k*512 + j];
    int b = b0 + ty;
    float hv = tanhf(acc);
    S.z[b*640 + 128 + j] = hv;
    __nv_bfloat16 hi = __float2bfloat16(hv);
    S.hsphi[b*512 + j] = hi;
    S.hsplo[b*512 + j] = __float2bfloat16(hv - __bfloat162float(hi));
    S.c[b*512 + j] = style_emb[(size_t)label[b]*512 + j];
}

// ---------------------------------------------------------------------------
// reduce gates K-split partials + bias, then LSTM cell (i,f,g,o)
// ---------------------------------------------------------------------------
__global__ void k_cellred(const float* __restrict__ dec_b){
    int b = blockIdx.x, j = threadIdx.x;   // 64 blocks x 512 threads
    float gi = dec_b[j], gf = dec_b[512+j], gg = dec_b[1024+j], go = dec_b[1536+j];
    #pragma unroll
    for (int z=0; z<KSPLIT; z++){
        const float* g = S.gpart + (size_t)z*(BB*2048) + b*2048;
        gi += g[j]; gf += g[512+j]; gg += g[1024+j]; go += g[1536+j];
    }
    float c = sigf(gf)*S.c[b*512+j] + sigf(gi)*tanhf(gg);
    S.c[b*512+j] = c;
    S.hstar[b*512+j] = sigf(go)*tanhf(c);
}

// ---------------------------------------------------------------------------
// attention with fused q K-split reduce + bias/scale. grid (NH, B), 64 thr.
// ---------------------------------------------------------------------------
__global__ void k_attn(const float* __restrict__ bq){
    int h = blockIdx.x, b = blockIdx.y;
    int l = threadIdx.x;   // 64
    __shared__ float sq[64], sc[64], red[64];
    {
        int j = h*64 + l;
        float qv = bq[j];
        #pragma unroll
        for (int z=0; z<KSPLIT; z++)
            qv += S.qpart[(size_t)z*(BB*512) + b*512 + j];
        sq[l] = qv * 0.125f;
    }
    __syncthreads();
    const float* kp = S.kv + ((size_t)l*BB + b)*1024 + h*64;
    float s = 0.f;
    #pragma unroll
    for (int d=0;d<64;d++) s += sq[d]*kp[d];
    sc[l] = s; red[l] = s;
    __syncthreads();
    for (int off=32; off; off>>=1){
        if (l < off) red[l] = fmaxf(red[l], red[l+off]);
        __syncthreads();
    }
    float m = red[0];
    __syncthreads();
    float e = expf(s - m);
    sc[l] = e; red[l] = e;
    __syncthreads();
    for (int off=32; off; off>>=1){
        if (l < off) red[l] += red[l+off];
        __syncthreads();
    }
    float inv = 1.f/red[0];
    int d = l;
    float acc = 0.f;
    #pragma unroll 4
    for (int l2=0;l2<64;l2++)
        acc += sc[l2] * S.kv[((size_t)l2*BB + b)*1024 + 512 + h*64 + d];
    S.ctx[b*512 + h*64 + d] = acc * inv;
}

// ---------------------------------------------------------------------------
// reduce attn-out K-split partials + bias + residual, LayerNorm,
// write z[:,128:640] and bf16 hi/lo split for the proj GEMM.
// ---------------------------------------------------------------------------
__global__ void k_outln(const float* __restrict__ ob,
                        const float* __restrict__ lng, const float* __restrict__ lnb){
    int b = blockIdx.x, j = threadIdx.x;   // 64 blocks x 512 threads
    float y = S.hstar[b*512 + j] + ob[j];
    #pragma unroll
    for (int z=0; z<KSPLIT; z++)
        y += S.opart[(size_t)z*(BB*512) + b*512 + j];

    float v1 = y, v2 = y*y;
    #pragma unroll
    for (int off=16; off; off>>=1){
        v1 += __shfl_down_sync(0xffffffffu, v1, off);
        v2 += __shfl_down_sync(0xffffffffu, v2, off);
    }
    __shared__ float s1[16], s2[16];
    __shared__ float mb[2];
    int wid = j >> 5, lane = j & 31;
    if (!lane){ s1[wid] = v1; s2[wid] = v2; }
    __syncthreads();
    if (j == 0){
        float a=0.f, cq=0.f;
        #pragma unroll
        for (int i=0;i<16;i++){ a += s1[i]; cq += s2[i]; }
        float mean = a*(1.f/512.f);
        float var  = cq*(1.f/512.f) - mean*mean;
        mb[0] = mean; mb[1] = rsqrtf(var + 1e-5f);
    }
    __syncthreads();
    float hv = (y - mb[0])*mb[1]*lng[j] + lnb[j];
    S.z[b*640 + 128 + j] = hv;
    __nv_bfloat16 hi = __float2bfloat16(hv);
    S.hsphi[b*512 + j] = hi;
    S.hsplo[b*512 + j] = __float2bfloat16(hv - __bfloat162float(hi));
}

// ---------------------------------------------------------------------------
// argmax reduce over NPROJ partials + embedding feedback -> z[:,0:128]
// ---------------------------------------------------------------------------
__global__ void k_feedback(const float* __restrict__ tok_emb){
    int b = blockIdx.x, t = threadIdx.x;   // 128
    float best = -1e30f; int bi = 0x7fffffff;
    for (int i=t; i<NPROJ; i+=128){
        float v = S.pmax[b*512 + i]; int idx = S.pidx[b*512 + i];
        if (v > best || (v == best && idx < bi)){ best = v; bi = idx; }
    }
    __shared__ float sv[128]; __shared__ int si[128];
    sv[t] = best; si[t] = bi;
    __syncthreads();
    for (int off=64; off; off>>=1){
        if (t < off){
            if (sv[t+off] > sv[t] || (sv[t+off] == sv[t] && si[t+off] < si[t])){
                sv[t] = sv[t+off]; si[t] = si[t+off];
            }
        }
        __syncthreads();
    }
    int tok = si[0];
    S.z[b*640 + t] = tok_emb[(size_t)tok*DEMB + t];
}

// ---------------------------------------------------------------------------
// host launch
// ---------------------------------------------------------------------------
extern "C" void kernel_launch(void* const* d_in, const int* in_sizes, int n_in,
                              void* d_out, int out_size){
    const int*   nx         = (const int*)  d_in[0];
    const int*   label      = (const int*)  d_in[1];
    const float* start_emb  = (const float*)d_in[2];
    const float* tok_emb    = (const float*)d_in[3];
    const float* style_emb  = (const float*)d_in[4];
    const float* enc_Wih_f  = (const float*)d_in[5];
    const float* enc_Whh_f  = (const float*)d_in[6];
    const float* enc_b_f    = (const float*)d_in[7];
    const float* enc_Wih_b  = (const float*)d_in[8];
    const float* enc_Whh_b  = (const float*)d_in[9];
    const float* enc_b_b    = (const float*)d_in[10];
    const float* transfer_W = (const float*)d_in[11];
    const float* dec_Wih    = (const float*)d_in[12];
    const float* dec_Whh    = (const float*)d_in[13];
    const float* dec_b      = (const float*)d_in[14];
    const float* attn_in_w  = (const float*)d_in[15];
    const float* attn_in_b  = (const float*)d_in[16];
    const float* attn_out_w = (const float*)d_in[17];
    const float* attn_out_b = (const float*)d_in[18];
    const float* proj_W     = (const float*)d_in[19];
    const float* proj_b     = (const float*)d_in[20];
    const float* ln_g       = (const float*)d_in[21];
    const float* ln_b       = (const float*)d_in[22];
    float* out = (float*)d_out;

    Scratch* sp;
    cudaGetSymbolAddress((void**)&sp, S);
    cudaFuncSetAttribute(k_gemmtc, cudaFuncAttributeMaxDynamicSharedMemorySize, GEMMTC_SMEM);
    cudaFuncSetAttribute(k_gemmtc, cudaFuncAttributePreferredSharedMemoryCarveout, 100);

    dim3 tb(32, 8);

    // ---- setup ----
    k_init<<<64, 256>>>(start_emb);
    k_embed<<<LL*BB, 128>>>(nx, tok_emb);
    k_wsplit<<<4096, 256>>>(proj_W);
    k_wihsplit<<<(1024*128+255)/256, 256>>>(enc_Wih_f, 0);
    k_wihsplit<<<(1024*128+255)/256, 256>>>(enc_Wih_b, 1);
    k_packencwhh<<<(256*256+255)/256, 256>>>(enc_Whh_f, 0);
    k_packencwhh<<<(256*256+255)/256, 256>>>(enc_Whh_b, 1);
    k_packkvsp<<<(1024*512+255)/256, 256>>>(attn_in_w);

    k_transpose<<<dim3(64,  4),  tb>>>(dec_Wih,   0, 2048, 128, sp->WdecT,             2048);
    k_transpose<<<dim3(64, 16),  tb>>>(dec_Whh,   0, 2048, 512, sp->WdecT + 128*2048,  2048);
    k_transpose<<<dim3(16, 16),  tb>>>(attn_in_w,    0, 512, 512, sp->WqT,              512);
    k_transpose<<<dim3(16, 16),  tb>>>(attn_out_w,   0, 512, 512, sp->WoutT,            512);
    k_transpose<<<dim3(16, 16),  tb>>>(transfer_W,   0, 512, 512, sp->transferT,        512);

    // Xpre = x @ Wihsp^T   (M=4096, N=2048, K=128) — wmma split-bf16,
    // columns gate-interleaved (dir*1024 + j*4 + g)
    k_gemmtc<<<dim3(16, 64), 256, GEMMTC_SMEM>>>(sp->xhi, sp->xlo, sp->Wihsphi, sp->Wihsplo,
                                                 128, nullptr, sp->Xpre, 2048LL,
                                                 nullptr, nullptr);

    // ---- encoder recurrence: ONE persistent launch (64 co-resident blocks) ----
    k_encoder<<<64, 256>>>(enc_b_f, enc_b_b);

    // h0 / c0
    k_h0<<<dim3(16, 8), 256>>>(label, style_emb);

    // k,v = memory @ Wkvsp^T + [bk|bv]   (M=4096, N=1024, K=512) — wmma
    k_gemmtc<<<dim3(8, 64), 256, GEMMTC_SMEM>>>(sp->memhi, sp->memlo, sp->Wkvsphi, sp->Wkvsplo,
                                                512, attn_in_b + 512, sp->kv, 1024LL,
                                                nullptr, nullptr);

    // ---- decoder: 8 launches/step ----
    for (int t=0; t<TT; t++){
        // gates partials: z @ WdecT   (M=64, N=2048, K=640, split 4x160)
        k_sgemm<<<dim3(32, 1, KSPLIT), 256>>>(sp->z, 640, sp->WdecT, 2048,
                                              sp->gpart, 2048, (long long)BB*2048,
                                              640, 160);
        k_cellred<<<64, 512>>>(dec_b);

        // q partials: h* @ WqT  (M=64, N=512, K=512, split 4x128)
        k_sgemm<<<dim3(8, 1, KSPLIT), 256>>>(sp->hstar, 512, sp->WqT, 512,
                                             sp->qpart, 512, (long long)BB*512,
                                             512, 128);
        k_attn<<<dim3(NHH, BB), 64>>>(attn_in_b);

        // out partials: ctx @ WoutT  (M=64, N=512, K=512, split 4x128)
        k_sgemm<<<dim3(8, 1, KSPLIT), 256>>>(sp->ctx, 512, sp->WoutT, 512,
                                             sp->opart, 512, (long long)BB*512,
                                             512, 128);
        k_outln<<<64, 512>>>(attn_out_b, ln_g, ln_b);

        // logits[:,t,:] = h @ proj_W^T + proj_b  (wmma split-bf16 + argmax)
        k_gemmtc<<<dim3(NPROJ, 1), 256, GEMMTC_SMEM>>>(sp->hsphi, sp->hsplo, sp->Whi, sp->Wlo,
                                                       512, proj_b, out + (size_t)t*VV,
                                                       (long long)TT*VV, sp->pmax, sp->pidx);

        k_feedback<<<64, 128>>>(tok_emb);
    }
    (void)in_sizes; (void)n_in; (void)out_size;
}